// round 8
// baseline (speedup 1.0000x reference)
#include <cuda_runtime.h>
#include <cuda_fp16.h>
#include <math.h>
#include <stdint.h>

// ---------------- problem constants (fixed by setup_inputs) ----------------
#define BFRAMES   128          // B*T = 8*16
#define SEQ       256          // H*W = 16*16
#define DMODEL    1152
#define NHEADS    12
#define NGROUPS   4
#define HEADDIM   96
#define QKV_N     1920         // 12*96 + 2*4*96
#define MTOK      32768        // BFRAMES*SEQ
#define SM_SCALE  0.1020620726159658f   // 96^-0.5

// ---------------- scratch (device globals; no allocation allowed) ----------
__device__ __half g_xh[(size_t)MTOK * DMODEL];      // fp16 x
__device__ __half g_wh[(size_t)QKV_N * DMODEL];     // fp16 weights (reused)
__device__ __half g_qh[(size_t)BFRAMES * NHEADS * SEQ * HEADDIM];
__device__ __half g_kh[(size_t)BFRAMES * NGROUPS * SEQ * HEADDIM];
__device__ __half g_vh[(size_t)BFRAMES * NGROUPS * SEQ * HEADDIM];
__device__ __half g_oh[(size_t)MTOK * DMODEL];      // fp16 attention output

// ============================================================================
// helpers
// ============================================================================
__device__ __forceinline__ uint32_t smem_u32(const void* p) {
    uint32_t a;
    asm("{ .reg .u64 t; cvta.to.shared.u64 t, %1; cvt.u32.u64 %0, t; }"
        : "=r"(a) : "l"(p));
    return a;
}

__device__ __forceinline__ void cp_async16(uint32_t saddr, const void* gptr) {
    asm volatile("cp.async.cg.shared.global [%0], [%1], 16;" :: "r"(saddr), "l"(gptr));
}

__device__ __forceinline__ void mma_f16(float c[4], const uint32_t a[4],
                                        const uint32_t b[2]) {
    asm volatile(
        "mma.sync.aligned.m16n8k16.row.col.f32.f16.f16.f32 "
        "{%0,%1,%2,%3}, {%4,%5,%6,%7}, {%8,%9}, {%0,%1,%2,%3};"
        : "+f"(c[0]), "+f"(c[1]), "+f"(c[2]), "+f"(c[3])
        : "r"(a[0]), "r"(a[1]), "r"(a[2]), "r"(a[3]), "r"(b[0]), "r"(b[1]));
}

__device__ __forceinline__ void ldsm4(uint32_t r[4], uint32_t addr) {
    asm volatile("ldmatrix.sync.aligned.m8n8.x4.shared.b16 {%0,%1,%2,%3}, [%4];"
                 : "=r"(r[0]), "=r"(r[1]), "=r"(r[2]), "=r"(r[3]) : "r"(addr));
}

__device__ __forceinline__ void ldsm4t(uint32_t r[4], uint32_t addr) {
    asm volatile("ldmatrix.sync.aligned.m8n8.x4.trans.shared.b16 {%0,%1,%2,%3}, [%4];"
                 : "=r"(r[0]), "=r"(r[1]), "=r"(r[2]), "=r"(r[3]) : "r"(addr));
}

// ============================================================================
// QKV GEMM with FUSED norm+RoPE+transpose epilogue.
// C-tile per CTA: 256 tokens x 96 cols = one full head column-block.
// blockIdx.x = hc (0..19): hc<12 -> Q head hc; 12..15 -> K group; 16..19 -> V.
// Mainloop: BK=64, 3-stage cp.async, 8 warps (warp tile 64x48), ldmatrix.
// Epilogue: stage fp32 acc to smem, per-row qk-norm + spatial RoPE, store fp16
// directly to g_qh/g_kh/g_vh in [bf, head, s, d] layout.
// ============================================================================
#define HSTR       72
#define QKV_STAGE_H ((256 + 96) * HSTR)        // 25344 halves
#define QKV_SMEM    (3 * QKV_STAGE_H * 2)      // 152064 bytes (>= 256*100*4 staging)
#define SSTR       100

__global__ __launch_bounds__(256, 1)
void gemm_qkv_fused(const __half* __restrict__ A, const __half* __restrict__ B)
{
    extern __shared__ __half smh[];
    const int tid    = threadIdx.x;
    const int lane   = tid & 31;
    const int wid    = tid >> 5;
    const int warp_m = wid & 3;
    const int warp_n = wid >> 2;
    const int hc = blockIdx.x;           // head-column block (0..19)
    const int m0 = blockIdx.y * 256;
    const int K = DMODEL;
    const int ITERS = DMODEL / 64;       // 18

    const __half* Ag = A + (size_t)m0 * K;
    const __half* Bg = B + (size_t)(hc * 96) * K;
    const uint32_t sbase = smem_u32(smh);

    auto load_stage = [&](int chunk, int st) {
        uint32_t abase = sbase + st * (QKV_STAGE_H * 2);
        uint32_t bbase = abase + 256 * (HSTR * 2);
        const __half* Ac = Ag + chunk * 64;
        const __half* Bc = Bg + chunk * 64;
#pragma unroll
        for (int j = 0; j < 8; j++) {            // A: 256 rows x 8 chunks of 16B
            int idx = tid + j * 256;
            int row = idx >> 3, c = idx & 7;
            cp_async16(abase + row * (HSTR * 2) + c * 16,
                       Ac + (size_t)row * K + c * 8);
        }
#pragma unroll
        for (int j = 0; j < 3; j++) {            // B: 96 rows x 8 chunks of 16B
            int idx = tid + j * 256;
            int row = idx >> 3, c = idx & 7;
            cp_async16(bbase + row * (HSTR * 2) + c * 16,
                       Bc + (size_t)row * K + c * 8);
        }
    };

    float acc[4][6][4];
#pragma unroll
    for (int mt = 0; mt < 4; mt++)
#pragma unroll
        for (int nt = 0; nt < 6; nt++)
#pragma unroll
            for (int r = 0; r < 4; r++) acc[mt][nt][r] = 0.f;

    const int arow = warp_m * 64 + (lane & 15);
    const int acol = (lane >> 4) * 8;
    const int brow = warp_n * 48 + (lane & 7) + (lane >> 4) * 8;
    const int bcol = ((lane >> 3) & 1) * 8;

    load_stage(0, 0);
    asm volatile("cp.async.commit_group;");
    load_stage(1, 1);
    asm volatile("cp.async.commit_group;");

    for (int i = 0; i < ITERS; i++) {
        asm volatile("cp.async.wait_group 1;");
        __syncthreads();

        if (i + 2 < ITERS) load_stage(i + 2, (i + 2) % 3);
        asm volatile("cp.async.commit_group;");

        const int st = i % 3;
        uint32_t abase = sbase + st * (QKV_STAGE_H * 2);
        uint32_t bbase = abase + 256 * (HSTR * 2);

#pragma unroll
        for (int kstep = 0; kstep < 4; kstep++) {
            uint32_t af[4][4];
#pragma unroll
            for (int mt = 0; mt < 4; mt++)
                ldsm4(af[mt], abase + ((arow + mt * 16) * HSTR
                                       + kstep * 16 + acol) * 2);
            uint32_t bf[6][2];
#pragma unroll
            for (int ntp = 0; ntp < 3; ntp++) {
                uint32_t r[4];
                ldsm4(r, bbase + ((brow + ntp * 16) * HSTR
                                  + kstep * 16 + bcol) * 2);
                bf[2 * ntp][0] = r[0]; bf[2 * ntp][1] = r[1];
                bf[2 * ntp + 1][0] = r[2]; bf[2 * ntp + 1][1] = r[3];
            }
#pragma unroll
            for (int mt = 0; mt < 4; mt++)
#pragma unroll
                for (int nt = 0; nt < 6; nt++)
                    mma_f16(acc[mt][nt], af[mt], bf[nt]);
        }
    }

    // ---- fused epilogue: stage acc tile, norm+rope per row, store fp16 ----
    __syncthreads();   // all warps done reading stage smem
    float* S = (float*)smh;   // [256][SSTR]
#pragma unroll
    for (int mt = 0; mt < 4; mt++) {
        int r0 = warp_m * 64 + mt * 16 + (lane >> 2);
#pragma unroll
        for (int nt = 0; nt < 6; nt++) {
            int col = warp_n * 48 + nt * 8 + (lane & 3) * 2;
            *(float2*)(S + r0 * SSTR + col) =
                make_float2(acc[mt][nt][0], acc[mt][nt][1]);
            *(float2*)(S + (r0 + 8) * SSTR + col) =
                make_float2(acc[mt][nt][2], acc[mt][nt][3]);
        }
    }
    __syncthreads();

    const bool is_q = (hc < 12);
    const bool is_k = (hc >= 12) && (hc < 16);
    const bool do_nr = hc < 16;
    // per-lane rope constants
    const int ri = lane & 15;
    const float invf = exp2f(-(float)ri * 0.8304820237218406f);

    for (int rr = 0; rr < 32; rr++) {
        int r = wid * 32 + rr;
        int t = m0 + r;
        int bf = t >> 8, s = t & 255;

        float x0 = S[r * SSTR + lane];
        float x1 = S[r * SSTR + lane + 32];
        float x2 = S[r * SSTR + lane + 64];

        if (do_nr) {
            float ss = fmaf(x0, x0, fmaf(x1, x1, x2 * x2));
#pragma unroll
            for (int o = 16; o; o >>= 1) ss += __shfl_xor_sync(0xffffffffu, ss, o);
            float inv = 1.0f / fmaxf(sqrtf(ss), 1e-10f);
            x0 *= inv; x1 *= inv; x2 *= inv;

            float pos = (float)((s >> 4) + (s & 15));
            float a = __shfl_sync(0xffffffffu, x0, 2 * ri);
            float b = __shfl_sync(0xffffffffu, x0, 2 * ri + 1);
            float ang = pos * invf;
            float sn, cs;
            __sincosf(ang, &sn, &cs);
            x0 = (lane < 16) ? fmaf(a, cs, -b * sn) : fmaf(a, sn, b * cs);
        }

        __half* dst;
        if (is_q)
            dst = g_qh + ((size_t)(bf * NHEADS + hc) * SEQ + s) * HEADDIM;
        else if (is_k)
            dst = g_kh + ((size_t)(bf * NGROUPS + (hc - 12)) * SEQ + s) * HEADDIM;
        else
            dst = g_vh + ((size_t)(bf * NGROUPS + (hc - 16)) * SEQ + s) * HEADDIM;

        dst[lane]      = __float2half_rn(x0);
        dst[lane + 32] = __float2half_rn(x1);
        dst[lane + 64] = __float2half_rn(x2);
    }
}

// ============================================================================
// fp16 mma.sync GEMM (NT) for the output projection (R7-proven).
// CTA 256x128, BK=64, 3-stage, single barrier per iter.
// ============================================================================
#define STAGE_H   ((256 + 128) * HSTR)       // 27648 halves
#define GEMM_SMEM (3 * STAGE_H * 2)          // 165888 bytes

__global__ __launch_bounds__(256, 1)
void gemm_f16(const __half* __restrict__ A, const __half* __restrict__ B,
              float* __restrict__ C, int ldC, int K)
{
    extern __shared__ __half smh[];
    const int tid    = threadIdx.x;
    const int lane   = tid & 31;
    const int wid    = tid >> 5;
    const int warp_m = wid & 3;
    const int warp_n = wid >> 2;
    const int m0 = blockIdx.y * 256;
    const int n0 = blockIdx.x * 128;
    const int ITERS = K >> 6;

    const __half* Ag = A + (size_t)m0 * K;
    const __half* Bg = B + (size_t)n0 * K;
    const uint32_t sbase = smem_u32(smh);

    auto load_stage = [&](int chunk, int st) {
        uint32_t abase = sbase + st * (STAGE_H * 2);
        uint32_t bbase = abase + 256 * (HSTR * 2);
        const __half* Ac = Ag + chunk * 64;
        const __half* Bc = Bg + chunk * 64;
#pragma unroll
        for (int j = 0; j < 8; j++) {
            int idx = tid + j * 256;
            int row = idx >> 3, c = idx & 7;
            cp_async16(abase + row * (HSTR * 2) + c * 16,
                       Ac + (size_t)row * K + c * 8);
        }
#pragma unroll
        for (int j = 0; j < 4; j++) {
            int idx = tid + j * 256;
            int row = idx >> 3, c = idx & 7;
            cp_async16(bbase + row * (HSTR * 2) + c * 16,
                       Bc + (size_t)row * K + c * 8);
        }
    };

    float acc[4][8][4];
#pragma unroll
    for (int mt = 0; mt < 4; mt++)
#pragma unroll
        for (int nt = 0; nt < 8; nt++)
#pragma unroll
            for (int r = 0; r < 4; r++) acc[mt][nt][r] = 0.f;

    const int arow = warp_m * 64 + (lane & 15);
    const int acol = (lane >> 4) * 8;
    const int brow = warp_n * 64 + (lane & 7) + (lane >> 4) * 8;
    const int bcol = ((lane >> 3) & 1) * 8;

    load_stage(0, 0);
    asm volatile("cp.async.commit_group;");
    if (ITERS > 1) load_stage(1, 1);
    asm volatile("cp.async.commit_group;");

    for (int i = 0; i < ITERS; i++) {
        asm volatile("cp.async.wait_group 1;");
        __syncthreads();

        if (i + 2 < ITERS) load_stage(i + 2, (i + 2) % 3);
        asm volatile("cp.async.commit_group;");

        const int st = i % 3;
        uint32_t abase = sbase + st * (STAGE_H * 2);
        uint32_t bbase = abase + 256 * (HSTR * 2);

#pragma unroll
        for (int kstep = 0; kstep < 4; kstep++) {
            uint32_t af[4][4];
#pragma unroll
            for (int mt = 0; mt < 4; mt++)
                ldsm4(af[mt], abase + ((arow + mt * 16) * HSTR
                                       + kstep * 16 + acol) * 2);
            uint32_t bf[8][2];
#pragma unroll
            for (int ntp = 0; ntp < 4; ntp++) {
                uint32_t r[4];
                ldsm4(r, bbase + ((brow + ntp * 16) * HSTR
                                  + kstep * 16 + bcol) * 2);
                bf[2 * ntp][0] = r[0]; bf[2 * ntp][1] = r[1];
                bf[2 * ntp + 1][0] = r[2]; bf[2 * ntp + 1][1] = r[3];
            }
#pragma unroll
            for (int mt = 0; mt < 4; mt++)
#pragma unroll
                for (int nt = 0; nt < 8; nt++)
                    mma_f16(acc[mt][nt], af[mt], bf[nt]);
        }
    }

#pragma unroll
    for (int mt = 0; mt < 4; mt++) {
        int row0 = m0 + warp_m * 64 + mt * 16 + (lane >> 2);
#pragma unroll
        for (int nt = 0; nt < 8; nt++) {
            int col = n0 + warp_n * 64 + nt * 8 + (lane & 3) * 2;
            *(float2*)(C + (size_t)row0 * ldC + col) =
                make_float2(acc[mt][nt][0], acc[mt][nt][1]);
            *(float2*)(C + (size_t)(row0 + 8) * ldC + col) =
                make_float2(acc[mt][nt][2], acc[mt][nt][3]);
        }
    }
}

// ============================================================================
// convert fp32 -> fp16 (RN), 8 elems per thread
// ============================================================================
__global__ __launch_bounds__(256) void f32_to_f16_kernel(
    const float4* __restrict__ in, uint4* __restrict__ out, int n8)
{
    int i = blockIdx.x * blockDim.x + threadIdx.x;
    if (i >= n8) return;
    float4 a = in[2 * i], b = in[2 * i + 1];
    __half2 h0 = __float22half2_rn(make_float2(a.x, a.y));
    __half2 h1 = __float22half2_rn(make_float2(a.z, a.w));
    __half2 h2 = __float22half2_rn(make_float2(b.x, b.y));
    __half2 h3 = __float22half2_rn(make_float2(b.z, b.w));
    uint4 o;
    o.x = *(uint32_t*)&h0; o.y = *(uint32_t*)&h1;
    o.z = *(uint32_t*)&h2; o.w = *(uint32_t*)&h3;
    out[i] = o;
}

// ============================================================================
// Flash attention, fp16 mma.sync m16n8k16, fp32 accum/softmax (R6-proven)
// ============================================================================
#define KS 104
#define VS 104
#define PS 72

__global__ __launch_bounds__(256, 1) void attn_kernel()
{
    __shared__ __half sK[64 * KS];
    __shared__ __half sV[64 * VS];
    __shared__ __half sP[128 * PS];

    const int tid  = threadIdx.x;
    const int lane = tid & 31;
    const int wid  = tid >> 5;
    const int half = blockIdx.x;
    const int h    = blockIdx.y;
    const int bf   = blockIdx.z;
    const int g    = h / 3;

    const __half* Qg = g_qh + ((size_t)(bf * NHEADS + h) * SEQ + half * 128 + wid * 16) * HEADDIM;
    const __half* Kg = g_kh + (size_t)(bf * NGROUPS + g) * SEQ * HEADDIM;
    const __half* Vg = g_vh + (size_t)(bf * NGROUPS + g) * SEQ * HEADDIM;

    uint32_t qf[6][4];
    {
        const __half* q0 = Qg + (lane >> 2) * HEADDIM;
        const __half* q1 = Qg + ((lane >> 2) + 8) * HEADDIM;
        int cc = 2 * (lane & 3);
#pragma unroll
        for (int j = 0; j < 6; j++) {
            qf[j][0] = *(const uint32_t*)(q0 + j * 16 + cc);
            qf[j][1] = *(const uint32_t*)(q1 + j * 16 + cc);
            qf[j][2] = *(const uint32_t*)(q0 + j * 16 + 8 + cc);
            qf[j][3] = *(const uint32_t*)(q1 + j * 16 + 8 + cc);
        }
    }

    const uint32_t sKb = smem_u32(sK);
    const uint32_t sVb = smem_u32(sV);
    const uint32_t sPw = smem_u32(sP) + wid * 16 * PS * 2;
    __half* Pw = sP + wid * 16 * PS;

    const int idx  = lane >> 3;
    const int lrow = lane & 7;

    float m_a = -INFINITY, m_b = -INFINITY;
    float l_a = 0.f, l_b = 0.f;
    float oacc[12][4];
#pragma unroll
    for (int nt = 0; nt < 12; nt++)
#pragma unroll
        for (int r = 0; r < 4; r++) oacc[nt][r] = 0.f;

    for (int kt = 0; kt < 4; kt++) {
        __syncthreads();
        {
            const __half* Kc = Kg + (size_t)kt * 64 * HEADDIM;
            const __half* Vc = Vg + (size_t)kt * 64 * HEADDIM;
#pragma unroll
            for (int it = 0; it < 3; it++) {
                int i = tid + it * 256;
                int r = i / 12, c = (i % 12) * 8;
                *(uint4*)(sK + r * KS + c) = *(const uint4*)(Kc + r * HEADDIM + c);
                *(uint4*)(sV + r * VS + c) = *(const uint4*)(Vc + r * HEADDIM + c);
            }
        }
        __syncthreads();

        float sacc[8][4];
#pragma unroll
        for (int nt = 0; nt < 8; nt++)
#pragma unroll
            for (int r = 0; r < 4; r++) sacc[nt][r] = 0.f;

#pragma unroll
        for (int j = 0; j < 6; j++) {
#pragma unroll
            for (int nt2 = 0; nt2 < 4; nt2++) {
                uint32_t r[4];
                ldsm4(r, sKb + ((nt2 * 16 + (idx >> 1) * 8 + lrow) * KS
                                + j * 16 + (idx & 1) * 8) * 2);
                uint32_t b0[2] = {r[0], r[1]};
                uint32_t b1[2] = {r[2], r[3]};
                mma_f16(sacc[2 * nt2], qf[j], b0);
                mma_f16(sacc[2 * nt2 + 1], qf[j], b1);
            }
        }

        float tmax_a = -INFINITY, tmax_b = -INFINITY;
#pragma unroll
        for (int nt = 0; nt < 8; nt++) {
#pragma unroll
            for (int r = 0; r < 4; r++) sacc[nt][r] *= SM_SCALE;
            tmax_a = fmaxf(tmax_a, fmaxf(sacc[nt][0], sacc[nt][1]));
            tmax_b = fmaxf(tmax_b, fmaxf(sacc[nt][2], sacc[nt][3]));
        }
        tmax_a = fmaxf(tmax_a, __shfl_xor_sync(0xffffffffu, tmax_a, 1));
        tmax_a = fmaxf(tmax_a, __shfl_xor_sync(0xffffffffu, tmax_a, 2));
        tmax_b = fmaxf(tmax_b, __shfl_xor_sync(0xffffffffu, tmax_b, 1));
        tmax_b = fmaxf(tmax_b, __shfl_xor_sync(0xffffffffu, tmax_b, 2));

        float mn_a = fmaxf(m_a, tmax_a);
        float mn_b = fmaxf(m_b, tmax_b);
        float al_a = __expf(m_a - mn_a);
        float al_b = __expf(m_b - mn_b);
        m_a = mn_a; m_b = mn_b;

        __syncwarp();

        float sum_a = 0.f, sum_b = 0.f;
        {
            int r0 = (lane >> 2);
            int cc = 2 * (lane & 3);
#pragma unroll
            for (int nt = 0; nt < 8; nt++) {
                float p0 = __expf(sacc[nt][0] - mn_a);
                float p1 = __expf(sacc[nt][1] - mn_a);
                float p2 = __expf(sacc[nt][2] - mn_b);
                float p3 = __expf(sacc[nt][3] - mn_b);
                sum_a += p0 + p1;
                sum_b += p2 + p3;
                int col = nt * 8 + cc;
                *(__half2*)(Pw + r0 * PS + col) =
                    __float22half2_rn(make_float2(p0, p1));
                *(__half2*)(Pw + (r0 + 8) * PS + col) =
                    __float22half2_rn(make_float2(p2, p3));
            }
        }
        sum_a += __shfl_xor_sync(0xffffffffu, sum_a, 1);
        sum_a += __shfl_xor_sync(0xffffffffu, sum_a, 2);
        sum_b += __shfl_xor_sync(0xffffffffu, sum_b, 1);
        sum_b += __shfl_xor_sync(0xffffffffu, sum_b, 2);
        l_a = l_a * al_a + sum_a;
        l_b = l_b * al_b + sum_b;

#pragma unroll
        for (int nt = 0; nt < 12; nt++) {
            oacc[nt][0] *= al_a; oacc[nt][1] *= al_a;
            oacc[nt][2] *= al_b; oacc[nt][3] *= al_b;
        }

        __syncwarp();

#pragma unroll
        for (int jj = 0; jj < 4; jj++) {
            uint32_t af[4];
            ldsm4(af, sPw + (((idx & 1) * 8 + lrow) * PS
                             + jj * 16 + (idx >> 1) * 8) * 2);
#pragma unroll
            for (int dt2 = 0; dt2 < 6; dt2++) {
                uint32_t r[4];
                ldsm4t(r, sVb + ((jj * 16 + (idx & 1) * 8 + lrow) * VS
                                 + dt2 * 16 + (idx >> 1) * 8) * 2);
                uint32_t b0[2] = {r[0], r[1]};
                uint32_t b1[2] = {r[2], r[3]};
                mma_f16(oacc[2 * dt2], af, b0);
                mma_f16(oacc[2 * dt2 + 1], af, b1);
            }
        }
    }

    float invla = 1.0f / l_a;
    float invlb = 1.0f / l_b;
    int row0 = half * 128 + wid * 16 + (lane >> 2);
    __half* o0 = g_oh + (size_t)(bf * SEQ + row0) * DMODEL + h * HEADDIM;
    __half* o1 = g_oh + (size_t)(bf * SEQ + row0 + 8) * DMODEL + h * HEADDIM;
#pragma unroll
    for (int nt = 0; nt < 12; nt++) {
        int col = nt * 8 + 2 * (lane & 3);
        *(__half2*)(o0 + col) = __float22half2_rn(
            make_float2(oacc[nt][0] * invla, oacc[nt][1] * invla));
        *(__half2*)(o1 + col) = __float22half2_rn(
            make_float2(oacc[nt][2] * invlb, oacc[nt][3] * invlb));
    }
}

// ============================================================================
// launch
// ============================================================================
extern "C" void kernel_launch(void* const* d_in, const int* in_sizes, int n_in,
                              void* d_out, int out_size)
{
    const float* x     = (const float*)d_in[0];
    const float* w_qkv = (const float*)d_in[1];
    const float* w_o   = (const float*)d_in[2];
    float* out = (float*)d_out;

    __half *xh_p, *wh_p, *oh_p;
    cudaGetSymbolAddress((void**)&xh_p, g_xh);
    cudaGetSymbolAddress((void**)&wh_p, g_wh);
    cudaGetSymbolAddress((void**)&oh_p, g_oh);

    cudaFuncSetAttribute(gemm_qkv_fused,
                         cudaFuncAttributeMaxDynamicSharedMemorySize, QKV_SMEM);
    cudaFuncSetAttribute(gemm_f16,
                         cudaFuncAttributeMaxDynamicSharedMemorySize, GEMM_SMEM);

    int n8;

    // convert x -> fp16, w_qkv -> fp16
    n8 = MTOK * DMODEL / 8;
    f32_to_f16_kernel<<<(n8 + 255) / 256, 256>>>((const float4*)x, (uint4*)xh_p, n8);
    n8 = QKV_N * DMODEL / 8;
    f32_to_f16_kernel<<<(n8 + 255) / 256, 256>>>((const float4*)w_qkv, (uint4*)wh_p, n8);

    // 1+2) QKV projection fused with qk-norm + RoPE + transpose
    gemm_qkv_fused<<<dim3(QKV_N / 96, MTOK / 256), 256, QKV_SMEM>>>(xh_p, wh_p);

    // 3) flash attention (fp16 mma; writes fp16 g_oh)
    attn_kernel<<<dim3(2, NHEADS, BFRAMES), 256>>>();

    // convert w_o -> fp16
    n8 = DMODEL * DMODEL / 8;
    f32_to_f16_kernel<<<(n8 + 255) / 256, 256>>>((const float4*)w_o, (uint4*)wh_p, n8);

    // 4) output projection: out[32768,1152] = oh @ w_o^T  (fp32 out)
    gemm_f16<<<dim3(DMODEL / 128, MTOK / 256), 256, GEMM_SMEM>>>(
        oh_p, wh_p, out, DMODEL, DMODEL);
}

// round 9
// speedup vs baseline: 1.0668x; 1.0668x over previous
#include <cuda_runtime.h>
#include <cuda_fp16.h>
#include <math.h>
#include <stdint.h>

// ---------------- problem constants (fixed by setup_inputs) ----------------
#define BFRAMES   128          // B*T = 8*16
#define SEQ       256          // H*W = 16*16
#define DMODEL    1152
#define NHEADS    12
#define NGROUPS   4
#define HEADDIM   96
#define QKV_N     1920         // 12*96 + 2*4*96
#define MTOK      32768        // BFRAMES*SEQ
#define SM_SCALE  0.1020620726159658f   // 96^-0.5

// ---------------- scratch (device globals; no allocation allowed) ----------
__device__ __half g_xh[(size_t)MTOK * DMODEL];      // fp16 x
__device__ __half g_wh[(size_t)QKV_N * DMODEL];     // fp16 weights (reused)
__device__ __half g_qkvh[(size_t)MTOK * QKV_N];     // fp16 qkv
__device__ __half g_qh[(size_t)BFRAMES * NHEADS * SEQ * HEADDIM];
__device__ __half g_kh[(size_t)BFRAMES * NGROUPS * SEQ * HEADDIM];
__device__ __half g_vh[(size_t)BFRAMES * NGROUPS * SEQ * HEADDIM];
__device__ __half g_oh[(size_t)MTOK * DMODEL];      // fp16 attention output

// ============================================================================
// helpers
// ============================================================================
__device__ __forceinline__ uint32_t smem_u32(const void* p) {
    uint32_t a;
    asm("{ .reg .u64 t; cvta.to.shared.u64 t, %1; cvt.u32.u64 %0, t; }"
        : "=r"(a) : "l"(p));
    return a;
}

__device__ __forceinline__ void cp_async16(uint32_t saddr, const void* gptr) {
    asm volatile("cp.async.cg.shared.global [%0], [%1], 16;" :: "r"(saddr), "l"(gptr));
}

__device__ __forceinline__ void mma_f16(float c[4], const uint32_t a[4],
                                        const uint32_t b[2]) {
    asm volatile(
        "mma.sync.aligned.m16n8k16.row.col.f32.f16.f16.f32 "
        "{%0,%1,%2,%3}, {%4,%5,%6,%7}, {%8,%9}, {%0,%1,%2,%3};"
        : "+f"(c[0]), "+f"(c[1]), "+f"(c[2]), "+f"(c[3])
        : "r"(a[0]), "r"(a[1]), "r"(a[2]), "r"(a[3]), "r"(b[0]), "r"(b[1]));
}

__device__ __forceinline__ void ldsm4(uint32_t r[4], uint32_t addr) {
    asm volatile("ldmatrix.sync.aligned.m8n8.x4.shared.b16 {%0,%1,%2,%3}, [%4];"
                 : "=r"(r[0]), "=r"(r[1]), "=r"(r[2]), "=r"(r[3]) : "r"(addr));
}

__device__ __forceinline__ void ldsm4t(uint32_t r[4], uint32_t addr) {
    asm volatile("ldmatrix.sync.aligned.m8n8.x4.trans.shared.b16 {%0,%1,%2,%3}, [%4];"
                 : "=r"(r[0]), "=r"(r[1]), "=r"(r[2]), "=r"(r[3]) : "r"(addr));
}

// ============================================================================
// fp16 mma.sync GEMM (NT): C[M,N] = A[M,K] * B[N,K]^T, fp32 accumulate.
// CTA 256x128, BK=64, 3-stage cp.async, single __syncthreads per iter,
// 8 warps (warp tile 64x64), ldmatrix loads.  (R7-proven)
// ============================================================================
#define HSTR      72
#define STAGE_H   ((256 + 128) * HSTR)       // 27648 halves
#define GEMM_SMEM (3 * STAGE_H * 2)          // 165888 bytes

template <typename OT>
__global__ __launch_bounds__(256, 1)
void gemm_f16(const __half* __restrict__ A, const __half* __restrict__ B,
              OT* __restrict__ C, int ldC, int K)
{
    extern __shared__ __half smh[];
    const int tid    = threadIdx.x;
    const int lane   = tid & 31;
    const int wid    = tid >> 5;
    const int warp_m = wid & 3;
    const int warp_n = wid >> 2;
    const int m0 = blockIdx.y * 256;
    const int n0 = blockIdx.x * 128;
    const int ITERS = K >> 6;            // BK = 64

    const __half* Ag = A + (size_t)m0 * K;
    const __half* Bg = B + (size_t)n0 * K;
    const uint32_t sbase = smem_u32(smh);

    auto load_stage = [&](int chunk, int st) {
        uint32_t abase = sbase + st * (STAGE_H * 2);
        uint32_t bbase = abase + 256 * (HSTR * 2);
        const __half* Ac = Ag + chunk * 64;
        const __half* Bc = Bg + chunk * 64;
#pragma unroll
        for (int j = 0; j < 8; j++) {
            int idx = tid + j * 256;
            int row = idx >> 3, c = idx & 7;
            cp_async16(abase + row * (HSTR * 2) + c * 16,
                       Ac + (size_t)row * K + c * 8);
        }
#pragma unroll
        for (int j = 0; j < 4; j++) {
            int idx = tid + j * 256;
            int row = idx >> 3, c = idx & 7;
            cp_async16(bbase + row * (HSTR * 2) + c * 16,
                       Bc + (size_t)row * K + c * 8);
        }
    };

    float acc[4][8][4];
#pragma unroll
    for (int mt = 0; mt < 4; mt++)
#pragma unroll
        for (int nt = 0; nt < 8; nt++)
#pragma unroll
            for (int r = 0; r < 4; r++) acc[mt][nt][r] = 0.f;

    const int arow = warp_m * 64 + (lane & 15);
    const int acol = (lane >> 4) * 8;
    const int brow = warp_n * 64 + (lane & 7) + (lane >> 4) * 8;
    const int bcol = ((lane >> 3) & 1) * 8;

    load_stage(0, 0);
    asm volatile("cp.async.commit_group;");
    if (ITERS > 1) load_stage(1, 1);
    asm volatile("cp.async.commit_group;");

    for (int i = 0; i < ITERS; i++) {
        asm volatile("cp.async.wait_group 1;");
        __syncthreads();

        if (i + 2 < ITERS) load_stage(i + 2, (i + 2) % 3);
        asm volatile("cp.async.commit_group;");

        const int st = i % 3;
        uint32_t abase = sbase + st * (STAGE_H * 2);
        uint32_t bbase = abase + 256 * (HSTR * 2);

#pragma unroll
        for (int kstep = 0; kstep < 4; kstep++) {
            uint32_t af[4][4];
#pragma unroll
            for (int mt = 0; mt < 4; mt++)
                ldsm4(af[mt], abase + ((arow + mt * 16) * HSTR
                                       + kstep * 16 + acol) * 2);
            uint32_t bf[8][2];
#pragma unroll
            for (int ntp = 0; ntp < 4; ntp++) {
                uint32_t r[4];
                ldsm4(r, bbase + ((brow + ntp * 16) * HSTR
                                  + kstep * 16 + bcol) * 2);
                bf[2 * ntp][0] = r[0]; bf[2 * ntp][1] = r[1];
                bf[2 * ntp + 1][0] = r[2]; bf[2 * ntp + 1][1] = r[3];
            }
#pragma unroll
            for (int mt = 0; mt < 4; mt++)
#pragma unroll
                for (int nt = 0; nt < 8; nt++)
                    mma_f16(acc[mt][nt], af[mt], bf[nt]);
        }
    }

#pragma unroll
    for (int mt = 0; mt < 4; mt++) {
        int row0 = m0 + warp_m * 64 + mt * 16 + (lane >> 2);
#pragma unroll
        for (int nt = 0; nt < 8; nt++) {
            int col = n0 + warp_n * 64 + nt * 8 + (lane & 3) * 2;
            if constexpr (sizeof(OT) == 4) {
                *(float2*)((float*)C + (size_t)row0 * ldC + col) =
                    make_float2(acc[mt][nt][0], acc[mt][nt][1]);
                *(float2*)((float*)C + (size_t)(row0 + 8) * ldC + col) =
                    make_float2(acc[mt][nt][2], acc[mt][nt][3]);
            } else {
                *(__half2*)((__half*)C + (size_t)row0 * ldC + col) =
                    __float22half2_rn(make_float2(acc[mt][nt][0], acc[mt][nt][1]));
                *(__half2*)((__half*)C + (size_t)(row0 + 8) * ldC + col) =
                    __float22half2_rn(make_float2(acc[mt][nt][2], acc[mt][nt][3]));
            }
        }
    }
}

// ============================================================================
// convert fp32 -> fp16 (RN), 8 elems per thread
// ============================================================================
__global__ __launch_bounds__(256) void f32_to_f16_kernel(
    const float4* __restrict__ in, uint4* __restrict__ out, int n8)
{
    int i = blockIdx.x * blockDim.x + threadIdx.x;
    if (i >= n8) return;
    float4 a = in[2 * i], b = in[2 * i + 1];
    __half2 h0 = __float22half2_rn(make_float2(a.x, a.y));
    __half2 h1 = __float22half2_rn(make_float2(a.z, a.w));
    __half2 h2 = __float22half2_rn(make_float2(b.x, b.y));
    __half2 h3 = __float22half2_rn(make_float2(b.z, b.w));
    uint4 o;
    o.x = *(uint32_t*)&h0; o.y = *(uint32_t*)&h1;
    o.z = *(uint32_t*)&h2; o.w = *(uint32_t*)&h3;
    out[i] = o;
}

// ============================================================================
// norm + RoPE + layout transpose; fp16 in, fp16 out (math in fp32) (R7-proven)
// ============================================================================
__global__ __launch_bounds__(256) void normrope_kernel(const __half* __restrict__ qkv)
{
    const int NQv = MTOK * NHEADS;
    const int NKv = MTOK * NGROUPS;
    int wid  = (blockIdx.x * blockDim.x + threadIdx.x) >> 5;
    int lane = threadIdx.x & 31;
    if (wid >= NQv + 2 * NKv) return;

    const __half* src;
    __half* dst;
    int t;
    bool do_norm_rope = true;

    if (wid < NQv) {
        t = wid / NHEADS; int h = wid % NHEADS;
        src = qkv + (size_t)t * QKV_N + h * HEADDIM;
        int bf = t >> 8, s = t & 255;
        dst = g_qh + ((size_t)(bf * NHEADS + h) * SEQ + s) * HEADDIM;
    } else if (wid < NQv + NKv) {
        int v = wid - NQv; t = v / NGROUPS; int g = v % NGROUPS;
        src = qkv + (size_t)t * QKV_N + DMODEL + g * HEADDIM;
        int bf = t >> 8, s = t & 255;
        dst = g_kh + ((size_t)(bf * NGROUPS + g) * SEQ + s) * HEADDIM;
    } else {
        int v = wid - NQv - NKv; t = v / NGROUPS; int g = v % NGROUPS;
        src = qkv + (size_t)t * QKV_N + DMODEL + NGROUPS * HEADDIM + g * HEADDIM;
        int bf = t >> 8, s = t & 255;
        dst = g_vh + ((size_t)(bf * NGROUPS + g) * SEQ + s) * HEADDIM;
        do_norm_rope = false;
    }

    float x0 = __half2float(src[lane]);
    float x1 = __half2float(src[lane + 32]);
    float x2 = __half2float(src[lane + 64]);

    if (do_norm_rope) {
        float ss = fmaf(x0, x0, fmaf(x1, x1, x2 * x2));
#pragma unroll
        for (int o = 16; o; o >>= 1) ss += __shfl_xor_sync(0xffffffffu, ss, o);
        float inv = 1.0f / fmaxf(sqrtf(ss), 1e-10f);
        x0 *= inv; x1 *= inv; x2 *= inv;

        int s = t & 255;
        float pos = (float)((s >> 4) + (s & 15));
        int i = lane & 15;
        float a = __shfl_sync(0xffffffffu, x0, 2 * i);
        float b = __shfl_sync(0xffffffffu, x0, 2 * i + 1);
        float invf = exp2f(-(float)i * 0.8304820237218406f);
        float ang = pos * invf;
        float sn, cs;
        sincosf(ang, &sn, &cs);
        x0 = (lane < 16) ? fmaf(a, cs, -b * sn) : fmaf(a, sn, b * cs);
    }

    dst[lane]      = __float2half_rn(x0);
    dst[lane + 32] = __float2half_rn(x1);
    dst[lane + 64] = __float2half_rn(x2);
}

// ============================================================================
// Flash attention, fp16 mma.sync m16n8k16, fp32 accum/softmax.
// NEW: cp.async double-buffered K/V chunks (dynamic smem, 2 stages).
// ============================================================================
#define KS 104
#define VS 104
#define PS 72
#define KV_STG   (64 * (KS + VS))                       // halves per stage
#define ATTN_SMEM ((2 * KV_STG + 128 * PS) * 2)         // 71680 bytes

__global__ __launch_bounds__(256, 1) void attn_kernel()
{
    extern __shared__ __half smh[];
    const uint32_t sbase = smem_u32(smh);

    const int tid  = threadIdx.x;
    const int lane = tid & 31;
    const int wid  = tid >> 5;
    const int half = blockIdx.x;
    const int h    = blockIdx.y;
    const int bf   = blockIdx.z;
    const int g    = h / 3;

    const __half* Qg = g_qh + ((size_t)(bf * NHEADS + h) * SEQ + half * 128 + wid * 16) * HEADDIM;
    const __half* Kg = g_kh + (size_t)(bf * NGROUPS + g) * SEQ * HEADDIM;
    const __half* Vg = g_vh + (size_t)(bf * NGROUPS + g) * SEQ * HEADDIM;

    uint32_t qf[6][4];
    {
        const __half* q0 = Qg + (lane >> 2) * HEADDIM;
        const __half* q1 = Qg + ((lane >> 2) + 8) * HEADDIM;
        int cc = 2 * (lane & 3);
#pragma unroll
        for (int j = 0; j < 6; j++) {
            qf[j][0] = *(const uint32_t*)(q0 + j * 16 + cc);
            qf[j][1] = *(const uint32_t*)(q1 + j * 16 + cc);
            qf[j][2] = *(const uint32_t*)(q0 + j * 16 + 8 + cc);
            qf[j][3] = *(const uint32_t*)(q1 + j * 16 + 8 + cc);
        }
    }

    const uint32_t sPw = sbase + (2 * KV_STG + wid * 16 * PS) * 2;
    __half* Pw = smh + 2 * KV_STG + wid * 16 * PS;

    const int idx  = lane >> 3;
    const int lrow = lane & 7;

    // async K/V chunk loader: 64 rows x 96 halves each, 3 x 16B per thread each
    auto load_kv = [&](int kt, int st) {
        uint32_t kb = sbase + st * (KV_STG * 2);
        uint32_t vb = kb + 64 * KS * 2;
        const __half* Kc = Kg + (size_t)kt * 64 * HEADDIM;
        const __half* Vc = Vg + (size_t)kt * 64 * HEADDIM;
#pragma unroll
        for (int it = 0; it < 3; it++) {
            int i = tid + it * 256;
            int r = i / 12, c = (i % 12) * 8;
            cp_async16(kb + (r * KS + c) * 2, Kc + r * HEADDIM + c);
            cp_async16(vb + (r * VS + c) * 2, Vc + r * HEADDIM + c);
        }
    };

    float m_a = -INFINITY, m_b = -INFINITY;
    float l_a = 0.f, l_b = 0.f;
    float oacc[12][4];
#pragma unroll
    for (int nt = 0; nt < 12; nt++)
#pragma unroll
        for (int r = 0; r < 4; r++) oacc[nt][r] = 0.f;

    load_kv(0, 0);
    asm volatile("cp.async.commit_group;");

    for (int kt = 0; kt < 4; kt++) {
        __syncthreads();   // all warps done reading buffer (kt+1)&1 (chunk kt-1)
        if (kt < 3) {
            load_kv(kt + 1, (kt + 1) & 1);
            asm volatile("cp.async.commit_group;");
            asm volatile("cp.async.wait_group 1;");
        } else {
            asm volatile("cp.async.wait_group 0;");
        }
        __syncthreads();   // chunk kt published

        const int st = kt & 1;
        const uint32_t sKb = sbase + st * (KV_STG * 2);
        const uint32_t sVb = sKb + 64 * KS * 2;

        // ---- S = Q K^T ----
        float sacc[8][4];
#pragma unroll
        for (int nt = 0; nt < 8; nt++)
#pragma unroll
            for (int r = 0; r < 4; r++) sacc[nt][r] = 0.f;

#pragma unroll
        for (int j = 0; j < 6; j++) {
#pragma unroll
            for (int nt2 = 0; nt2 < 4; nt2++) {
                uint32_t r[4];
                ldsm4(r, sKb + ((nt2 * 16 + (idx >> 1) * 8 + lrow) * KS
                                + j * 16 + (idx & 1) * 8) * 2);
                uint32_t b0[2] = {r[0], r[1]};
                uint32_t b1[2] = {r[2], r[3]};
                mma_f16(sacc[2 * nt2], qf[j], b0);
                mma_f16(sacc[2 * nt2 + 1], qf[j], b1);
            }
        }

        // ---- online softmax ----
        float tmax_a = -INFINITY, tmax_b = -INFINITY;
#pragma unroll
        for (int nt = 0; nt < 8; nt++) {
#pragma unroll
            for (int r = 0; r < 4; r++) sacc[nt][r] *= SM_SCALE;
            tmax_a = fmaxf(tmax_a, fmaxf(sacc[nt][0], sacc[nt][1]));
            tmax_b = fmaxf(tmax_b, fmaxf(sacc[nt][2], sacc[nt][3]));
        }
        tmax_a = fmaxf(tmax_a, __shfl_xor_sync(0xffffffffu, tmax_a, 1));
        tmax_a = fmaxf(tmax_a, __shfl_xor_sync(0xffffffffu, tmax_a, 2));
        tmax_b = fmaxf(tmax_b, __shfl_xor_sync(0xffffffffu, tmax_b, 1));
        tmax_b = fmaxf(tmax_b, __shfl_xor_sync(0xffffffffu, tmax_b, 2));

        float mn_a = fmaxf(m_a, tmax_a);
        float mn_b = fmaxf(m_b, tmax_b);
        float al_a = __expf(m_a - mn_a);
        float al_b = __expf(m_b - mn_b);
        m_a = mn_a; m_b = mn_b;

        __syncwarp();   // previous chunk's P reads done before overwrite

        float sum_a = 0.f, sum_b = 0.f;
        {
            int r0 = (lane >> 2);
            int cc = 2 * (lane & 3);
#pragma unroll
            for (int nt = 0; nt < 8; nt++) {
                float p0 = __expf(sacc[nt][0] - mn_a);
                float p1 = __expf(sacc[nt][1] - mn_a);
                float p2 = __expf(sacc[nt][2] - mn_b);
                float p3 = __expf(sacc[nt][3] - mn_b);
                sum_a += p0 + p1;
                sum_b += p2 + p3;
                int col = nt * 8 + cc;
                *(__half2*)(Pw + r0 * PS + col) =
                    __float22half2_rn(make_float2(p0, p1));
                *(__half2*)(Pw + (r0 + 8) * PS + col) =
                    __float22half2_rn(make_float2(p2, p3));
            }
        }
        sum_a += __shfl_xor_sync(0xffffffffu, sum_a, 1);
        sum_a += __shfl_xor_sync(0xffffffffu, sum_a, 2);
        sum_b += __shfl_xor_sync(0xffffffffu, sum_b, 1);
        sum_b += __shfl_xor_sync(0xffffffffu, sum_b, 2);
        l_a = l_a * al_a + sum_a;
        l_b = l_b * al_b + sum_b;

#pragma unroll
        for (int nt = 0; nt < 12; nt++) {
            oacc[nt][0] *= al_a; oacc[nt][1] *= al_a;
            oacc[nt][2] *= al_b; oacc[nt][3] *= al_b;
        }

        __syncwarp();   // P writes visible within warp

        // ---- O += P V ----
#pragma unroll
        for (int jj = 0; jj < 4; jj++) {
            uint32_t af[4];
            ldsm4(af, sPw + (((idx & 1) * 8 + lrow) * PS
                             + jj * 16 + (idx >> 1) * 8) * 2);
#pragma unroll
            for (int dt2 = 0; dt2 < 6; dt2++) {
                uint32_t r[4];
                ldsm4t(r, sVb + ((jj * 16 + (idx & 1) * 8 + lrow) * VS
                                 + dt2 * 16 + (idx >> 1) * 8) * 2);
                uint32_t b0[2] = {r[0], r[1]};
                uint32_t b1[2] = {r[2], r[3]};
                mma_f16(oacc[2 * dt2], af, b0);
                mma_f16(oacc[2 * dt2 + 1], af, b1);
            }
        }
    }

    float invla = 1.0f / l_a;
    float invlb = 1.0f / l_b;
    int row0 = half * 128 + wid * 16 + (lane >> 2);
    __half* o0 = g_oh + (size_t)(bf * SEQ + row0) * DMODEL + h * HEADDIM;
    __half* o1 = g_oh + (size_t)(bf * SEQ + row0 + 8) * DMODEL + h * HEADDIM;
#pragma unroll
    for (int nt = 0; nt < 12; nt++) {
        int col = nt * 8 + 2 * (lane & 3);
        *(__half2*)(o0 + col) = __float22half2_rn(
            make_float2(oacc[nt][0] * invla, oacc[nt][1] * invla));
        *(__half2*)(o1 + col) = __float22half2_rn(
            make_float2(oacc[nt][2] * invlb, oacc[nt][3] * invlb));
    }
}

// ============================================================================
// launch
// ============================================================================
extern "C" void kernel_launch(void* const* d_in, const int* in_sizes, int n_in,
                              void* d_out, int out_size)
{
    const float* x     = (const float*)d_in[0];
    const float* w_qkv = (const float*)d_in[1];
    const float* w_o   = (const float*)d_in[2];
    float* out = (float*)d_out;

    __half *xh_p, *wh_p, *qkvh_p, *oh_p;
    cudaGetSymbolAddress((void**)&xh_p, g_xh);
    cudaGetSymbolAddress((void**)&wh_p, g_wh);
    cudaGetSymbolAddress((void**)&qkvh_p, g_qkvh);
    cudaGetSymbolAddress((void**)&oh_p, g_oh);

    cudaFuncSetAttribute(gemm_f16<__half>,
                         cudaFuncAttributeMaxDynamicSharedMemorySize, GEMM_SMEM);
    cudaFuncSetAttribute(gemm_f16<float>,
                         cudaFuncAttributeMaxDynamicSharedMemorySize, GEMM_SMEM);
    cudaFuncSetAttribute(attn_kernel,
                         cudaFuncAttributeMaxDynamicSharedMemorySize, ATTN_SMEM);

    int n8;

    // convert x -> fp16, w_qkv -> fp16
    n8 = MTOK * DMODEL / 8;
    f32_to_f16_kernel<<<(n8 + 255) / 256, 256>>>((const float4*)x, (uint4*)xh_p, n8);
    n8 = QKV_N * DMODEL / 8;
    f32_to_f16_kernel<<<(n8 + 255) / 256, 256>>>((const float4*)w_qkv, (uint4*)wh_p, n8);

    // 1) QKV projection: qkvh[32768,1920] = xh @ w_qkv^T  (fp16 out)
    gemm_f16<__half><<<dim3(QKV_N / 128, MTOK / 256), 256, GEMM_SMEM>>>(
        xh_p, wh_p, qkvh_p, QKV_N, DMODEL);

    // 2) qk-norm + spatial RoPE + transpose (fp16 q/k/v)
    {
        int total_warps = MTOK * NHEADS + 2 * MTOK * NGROUPS;
        normrope_kernel<<<total_warps / 8, 256>>>(qkvh_p);
    }

    // 3) flash attention (fp16 mma, double-buffered K/V; writes fp16 g_oh)
    attn_kernel<<<dim3(2, NHEADS, BFRAMES), 256, ATTN_SMEM>>>();

    // convert w_o -> fp16
    n8 = DMODEL * DMODEL / 8;
    f32_to_f16_kernel<<<(n8 + 255) / 256, 256>>>((const float4*)w_o, (uint4*)wh_p, n8);

    // 4) output projection: out[32768,1152] = oh @ w_o^T  (fp32 out)
    gemm_f16<float><<<dim3(DMODEL / 128, MTOK / 256), 256, GEMM_SMEM>>>(
        oh_p, wh_p, out, DMODEL, DMODEL);
}

// round 10
// speedup vs baseline: 1.0895x; 1.0213x over previous
#include <cuda_runtime.h>
#include <cuda_fp16.h>
#include <math.h>
#include <stdint.h>

// ---------------- problem constants (fixed by setup_inputs) ----------------
#define BFRAMES   128          // B*T = 8*16
#define SEQ       256          // H*W = 16*16
#define DMODEL    1152
#define NHEADS    12
#define NGROUPS   4
#define HEADDIM   96
#define QKV_N     1920         // 12*96 + 2*4*96
#define MTOK      32768        // BFRAMES*SEQ
#define SM_SCALE  0.1020620726159658f   // 96^-0.5

// ---------------- scratch (device globals; no allocation allowed) ----------
__device__ __half g_xh[(size_t)MTOK * DMODEL];      // fp16 x
__device__ __half g_wh[(size_t)QKV_N * DMODEL];     // fp16 weights (reused)
__device__ __half g_qkvh[(size_t)MTOK * QKV_N];     // fp16 qkv
__device__ __half g_qh[(size_t)BFRAMES * NHEADS * SEQ * HEADDIM];
__device__ __half g_kh[(size_t)BFRAMES * NGROUPS * SEQ * HEADDIM];
__device__ __half g_vh[(size_t)BFRAMES * NGROUPS * SEQ * HEADDIM];
__device__ __half g_oh[(size_t)MTOK * DMODEL];      // fp16 attention output

// ============================================================================
// helpers
// ============================================================================
__device__ __forceinline__ uint32_t smem_u32(const void* p) {
    uint32_t a;
    asm("{ .reg .u64 t; cvta.to.shared.u64 t, %1; cvt.u32.u64 %0, t; }"
        : "=r"(a) : "l"(p));
    return a;
}

__device__ __forceinline__ void cp_async16(uint32_t saddr, const void* gptr) {
    asm volatile("cp.async.cg.shared.global [%0], [%1], 16;" :: "r"(saddr), "l"(gptr));
}

__device__ __forceinline__ void mma_f16(float c[4], const uint32_t a[4],
                                        const uint32_t b[2]) {
    asm volatile(
        "mma.sync.aligned.m16n8k16.row.col.f32.f16.f16.f32 "
        "{%0,%1,%2,%3}, {%4,%5,%6,%7}, {%8,%9}, {%0,%1,%2,%3};"
        : "+f"(c[0]), "+f"(c[1]), "+f"(c[2]), "+f"(c[3])
        : "r"(a[0]), "r"(a[1]), "r"(a[2]), "r"(a[3]), "r"(b[0]), "r"(b[1]));
}

__device__ __forceinline__ void ldsm4(uint32_t r[4], uint32_t addr) {
    asm volatile("ldmatrix.sync.aligned.m8n8.x4.shared.b16 {%0,%1,%2,%3}, [%4];"
                 : "=r"(r[0]), "=r"(r[1]), "=r"(r[2]), "=r"(r[3]) : "r"(addr));
}

__device__ __forceinline__ void ldsm4t(uint32_t r[4], uint32_t addr) {
    asm volatile("ldmatrix.sync.aligned.m8n8.x4.trans.shared.b16 {%0,%1,%2,%3}, [%4];"
                 : "=r"(r[0]), "=r"(r[1]), "=r"(r[2]), "=r"(r[3]) : "r"(addr));
}

// ============================================================================
// fp16 mma.sync GEMM (NT): C[M,N] = A[M,K] * B[N,K]^T, fp32 accumulate.
// CTA 256x128, BK=64, 3-stage cp.async, single __syncthreads per iter,
// 8 warps (warp tile 64x64), ldmatrix loads.  (R7-proven)
// ============================================================================
#define HSTR      72
#define STAGE_H   ((256 + 128) * HSTR)       // 27648 halves
#define GEMM_SMEM (3 * STAGE_H * 2)          // 165888 bytes

template <typename OT>
__global__ __launch_bounds__(256, 1)
void gemm_f16(const __half* __restrict__ A, const __half* __restrict__ B,
              OT* __restrict__ C, int ldC, int K)
{
    extern __shared__ __half smh[];
    const int tid    = threadIdx.x;
    const int lane   = tid & 31;
    const int wid    = tid >> 5;
    const int warp_m = wid & 3;
    const int warp_n = wid >> 2;
    const int m0 = blockIdx.y * 256;
    const int n0 = blockIdx.x * 128;
    const int ITERS = K >> 6;            // BK = 64

    const __half* Ag = A + (size_t)m0 * K;
    const __half* Bg = B + (size_t)n0 * K;
    const uint32_t sbase = smem_u32(smh);

    auto load_stage = [&](int chunk, int st) {
        uint32_t abase = sbase + st * (STAGE_H * 2);
        uint32_t bbase = abase + 256 * (HSTR * 2);
        const __half* Ac = Ag + chunk * 64;
        const __half* Bc = Bg + chunk * 64;
#pragma unroll
        for (int j = 0; j < 8; j++) {
            int idx = tid + j * 256;
            int row = idx >> 3, c = idx & 7;
            cp_async16(abase + row * (HSTR * 2) + c * 16,
                       Ac + (size_t)row * K + c * 8);
        }
#pragma unroll
        for (int j = 0; j < 4; j++) {
            int idx = tid + j * 256;
            int row = idx >> 3, c = idx & 7;
            cp_async16(bbase + row * (HSTR * 2) + c * 16,
                       Bc + (size_t)row * K + c * 8);
        }
    };

    float acc[4][8][4];
#pragma unroll
    for (int mt = 0; mt < 4; mt++)
#pragma unroll
        for (int nt = 0; nt < 8; nt++)
#pragma unroll
            for (int r = 0; r < 4; r++) acc[mt][nt][r] = 0.f;

    const int arow = warp_m * 64 + (lane & 15);
    const int acol = (lane >> 4) * 8;
    const int brow = warp_n * 64 + (lane & 7) + (lane >> 4) * 8;
    const int bcol = ((lane >> 3) & 1) * 8;

    load_stage(0, 0);
    asm volatile("cp.async.commit_group;");
    if (ITERS > 1) load_stage(1, 1);
    asm volatile("cp.async.commit_group;");

    for (int i = 0; i < ITERS; i++) {
        asm volatile("cp.async.wait_group 1;");
        __syncthreads();

        if (i + 2 < ITERS) load_stage(i + 2, (i + 2) % 3);
        asm volatile("cp.async.commit_group;");

        const int st = i % 3;
        uint32_t abase = sbase + st * (STAGE_H * 2);
        uint32_t bbase = abase + 256 * (HSTR * 2);

#pragma unroll
        for (int kstep = 0; kstep < 4; kstep++) {
            uint32_t af[4][4];
#pragma unroll
            for (int mt = 0; mt < 4; mt++)
                ldsm4(af[mt], abase + ((arow + mt * 16) * HSTR
                                       + kstep * 16 + acol) * 2);
            uint32_t bf[8][2];
#pragma unroll
            for (int ntp = 0; ntp < 4; ntp++) {
                uint32_t r[4];
                ldsm4(r, bbase + ((brow + ntp * 16) * HSTR
                                  + kstep * 16 + bcol) * 2);
                bf[2 * ntp][0] = r[0]; bf[2 * ntp][1] = r[1];
                bf[2 * ntp + 1][0] = r[2]; bf[2 * ntp + 1][1] = r[3];
            }
#pragma unroll
            for (int mt = 0; mt < 4; mt++)
#pragma unroll
                for (int nt = 0; nt < 8; nt++)
                    mma_f16(acc[mt][nt], af[mt], bf[nt]);
        }
    }

#pragma unroll
    for (int mt = 0; mt < 4; mt++) {
        int row0 = m0 + warp_m * 64 + mt * 16 + (lane >> 2);
#pragma unroll
        for (int nt = 0; nt < 8; nt++) {
            int col = n0 + warp_n * 64 + nt * 8 + (lane & 3) * 2;
            if constexpr (sizeof(OT) == 4) {
                *(float2*)((float*)C + (size_t)row0 * ldC + col) =
                    make_float2(acc[mt][nt][0], acc[mt][nt][1]);
                *(float2*)((float*)C + (size_t)(row0 + 8) * ldC + col) =
                    make_float2(acc[mt][nt][2], acc[mt][nt][3]);
            } else {
                *(__half2*)((__half*)C + (size_t)row0 * ldC + col) =
                    __float22half2_rn(make_float2(acc[mt][nt][0], acc[mt][nt][1]));
                *(__half2*)((__half*)C + (size_t)(row0 + 8) * ldC + col) =
                    __float22half2_rn(make_float2(acc[mt][nt][2], acc[mt][nt][3]));
            }
        }
    }
}

// ============================================================================
// convert fp32 -> fp16 (RN), 8 elems per thread
// ============================================================================
__global__ __launch_bounds__(256) void f32_to_f16_kernel(
    const float4* __restrict__ in, uint4* __restrict__ out, int n8)
{
    int i = blockIdx.x * blockDim.x + threadIdx.x;
    if (i >= n8) return;
    float4 a = in[2 * i], b = in[2 * i + 1];
    __half2 h0 = __float22half2_rn(make_float2(a.x, a.y));
    __half2 h1 = __float22half2_rn(make_float2(a.z, a.w));
    __half2 h2 = __float22half2_rn(make_float2(b.x, b.y));
    __half2 h3 = __float22half2_rn(make_float2(b.z, b.w));
    uint4 o;
    o.x = *(uint32_t*)&h0; o.y = *(uint32_t*)&h1;
    o.z = *(uint32_t*)&h2; o.w = *(uint32_t*)&h3;
    out[i] = o;
}

// ============================================================================
// norm + RoPE + layout transpose; fp16 in, fp16 out (math in fp32).
// NOW uses fast __sincosf (validated in R8 fused epilogue).
// ============================================================================
__global__ __launch_bounds__(256) void normrope_kernel(const __half* __restrict__ qkv)
{
    const int NQv = MTOK * NHEADS;
    const int NKv = MTOK * NGROUPS;
    int wid  = (blockIdx.x * blockDim.x + threadIdx.x) >> 5;
    int lane = threadIdx.x & 31;
    if (wid >= NQv + 2 * NKv) return;

    const __half* src;
    __half* dst;
    int t;
    bool do_norm_rope = true;

    if (wid < NQv) {
        t = wid / NHEADS; int h = wid % NHEADS;
        src = qkv + (size_t)t * QKV_N + h * HEADDIM;
        int bf = t >> 8, s = t & 255;
        dst = g_qh + ((size_t)(bf * NHEADS + h) * SEQ + s) * HEADDIM;
    } else if (wid < NQv + NKv) {
        int v = wid - NQv; t = v / NGROUPS; int g = v % NGROUPS;
        src = qkv + (size_t)t * QKV_N + DMODEL + g * HEADDIM;
        int bf = t >> 8, s = t & 255;
        dst = g_kh + ((size_t)(bf * NGROUPS + g) * SEQ + s) * HEADDIM;
    } else {
        int v = wid - NQv - NKv; t = v / NGROUPS; int g = v % NGROUPS;
        src = qkv + (size_t)t * QKV_N + DMODEL + NGROUPS * HEADDIM + g * HEADDIM;
        int bf = t >> 8, s = t & 255;
        dst = g_vh + ((size_t)(bf * NGROUPS + g) * SEQ + s) * HEADDIM;
        do_norm_rope = false;
    }

    float x0 = __half2float(src[lane]);
    float x1 = __half2float(src[lane + 32]);
    float x2 = __half2float(src[lane + 64]);

    if (do_norm_rope) {
        float ss = fmaf(x0, x0, fmaf(x1, x1, x2 * x2));
#pragma unroll
        for (int o = 16; o; o >>= 1) ss += __shfl_xor_sync(0xffffffffu, ss, o);
        float inv = 1.0f / fmaxf(sqrtf(ss), 1e-10f);
        x0 *= inv; x1 *= inv; x2 *= inv;

        int s = t & 255;
        float pos = (float)((s >> 4) + (s & 15));
        int i = lane & 15;
        float a = __shfl_sync(0xffffffffu, x0, 2 * i);
        float b = __shfl_sync(0xffffffffu, x0, 2 * i + 1);
        float invf = exp2f(-(float)i * 0.8304820237218406f);
        float ang = pos * invf;
        float sn, cs;
        __sincosf(ang, &sn, &cs);
        x0 = (lane < 16) ? fmaf(a, cs, -b * sn) : fmaf(a, sn, b * cs);
    }

    dst[lane]      = __float2half_rn(x0);
    dst[lane + 32] = __float2half_rn(x1);
    dst[lane + 64] = __float2half_rn(x2);
}

// ============================================================================
// Flash attention, fp16 mma.sync m16n8k16, fp32 accum/softmax.
// NOW: 128-thread CTAs (4 warps, 64 q-rows), 2 CTAs/SM for barrier overlap.
// cp.async double-buffered K/V (2 stages).
// ============================================================================
#define KS 104
#define VS 104
#define PS 72
#define KV_STG   (64 * (KS + VS))                       // halves per stage
#define ATTN_SMEM ((2 * KV_STG + 64 * PS) * 2)          // 62464 bytes

__global__ __launch_bounds__(128, 2) void attn_kernel()
{
    extern __shared__ __half smh[];
    const uint32_t sbase = smem_u32(smh);

    const int tid  = threadIdx.x;
    const int lane = tid & 31;
    const int wid  = tid >> 5;          // 0..3
    const int quarter = blockIdx.x;     // 0..3 (64 q-rows each)
    const int h    = blockIdx.y;
    const int bf   = blockIdx.z;
    const int g    = h / 3;

    const __half* Qg = g_qh + ((size_t)(bf * NHEADS + h) * SEQ
                               + quarter * 64 + wid * 16) * HEADDIM;
    const __half* Kg = g_kh + (size_t)(bf * NGROUPS + g) * SEQ * HEADDIM;
    const __half* Vg = g_vh + (size_t)(bf * NGROUPS + g) * SEQ * HEADDIM;

    uint32_t qf[6][4];
    {
        const __half* q0 = Qg + (lane >> 2) * HEADDIM;
        const __half* q1 = Qg + ((lane >> 2) + 8) * HEADDIM;
        int cc = 2 * (lane & 3);
#pragma unroll
        for (int j = 0; j < 6; j++) {
            qf[j][0] = *(const uint32_t*)(q0 + j * 16 + cc);
            qf[j][1] = *(const uint32_t*)(q1 + j * 16 + cc);
            qf[j][2] = *(const uint32_t*)(q0 + j * 16 + 8 + cc);
            qf[j][3] = *(const uint32_t*)(q1 + j * 16 + 8 + cc);
        }
    }

    const uint32_t sPw = sbase + (2 * KV_STG + wid * 16 * PS) * 2;
    __half* Pw = smh + 2 * KV_STG + wid * 16 * PS;

    const int idx  = lane >> 3;
    const int lrow = lane & 7;

    // async K/V chunk loader: 64 rows x 96 halves each; 128 threads, 6 iters
    auto load_kv = [&](int kt, int st) {
        uint32_t kb = sbase + st * (KV_STG * 2);
        uint32_t vb = kb + 64 * KS * 2;
        const __half* Kc = Kg + (size_t)kt * 64 * HEADDIM;
        const __half* Vc = Vg + (size_t)kt * 64 * HEADDIM;
#pragma unroll
        for (int it = 0; it < 6; it++) {
            int i = tid + it * 128;
            int r = i / 12, c = (i % 12) * 8;
            cp_async16(kb + (r * KS + c) * 2, Kc + r * HEADDIM + c);
            cp_async16(vb + (r * VS + c) * 2, Vc + r * HEADDIM + c);
        }
    };

    float m_a = -INFINITY, m_b = -INFINITY;
    float l_a = 0.f, l_b = 0.f;
    float oacc[12][4];
#pragma unroll
    for (int nt = 0; nt < 12; nt++)
#pragma unroll
        for (int r = 0; r < 4; r++) oacc[nt][r] = 0.f;

    load_kv(0, 0);
    asm volatile("cp.async.commit_group;");

    for (int kt = 0; kt < 4; kt++) {
        __syncthreads();   // all warps done reading the buffer being overwritten
        if (kt < 3) {
            load_kv(kt + 1, (kt + 1) & 1);
            asm volatile("cp.async.commit_group;");
            asm volatile("cp.async.wait_group 1;");
        } else {
            asm volatile("cp.async.wait_group 0;");
        }
        __syncthreads();   // chunk kt published

        const int st = kt & 1;
        const uint32_t sKb = sbase + st * (KV_STG * 2);
        const uint32_t sVb = sKb + 64 * KS * 2;

        // ---- S = Q K^T ----
        float sacc[8][4];
#pragma unroll
        for (int nt = 0; nt < 8; nt++)
#pragma unroll
            for (int r = 0; r < 4; r++) sacc[nt][r] = 0.f;

#pragma unroll
        for (int j = 0; j < 6; j++) {
#pragma unroll
            for (int nt2 = 0; nt2 < 4; nt2++) {
                uint32_t r[4];
                ldsm4(r, sKb + ((nt2 * 16 + (idx >> 1) * 8 + lrow) * KS
                                + j * 16 + (idx & 1) * 8) * 2);
                uint32_t b0[2] = {r[0], r[1]};
                uint32_t b1[2] = {r[2], r[3]};
                mma_f16(sacc[2 * nt2], qf[j], b0);
                mma_f16(sacc[2 * nt2 + 1], qf[j], b1);
            }
        }

        // ---- online softmax ----
        float tmax_a = -INFINITY, tmax_b = -INFINITY;
#pragma unroll
        for (int nt = 0; nt < 8; nt++) {
#pragma unroll
            for (int r = 0; r < 4; r++) sacc[nt][r] *= SM_SCALE;
            tmax_a = fmaxf(tmax_a, fmaxf(sacc[nt][0], sacc[nt][1]));
            tmax_b = fmaxf(tmax_b, fmaxf(sacc[nt][2], sacc[nt][3]));
        }
        tmax_a = fmaxf(tmax_a, __shfl_xor_sync(0xffffffffu, tmax_a, 1));
        tmax_a = fmaxf(tmax_a, __shfl_xor_sync(0xffffffffu, tmax_a, 2));
        tmax_b = fmaxf(tmax_b, __shfl_xor_sync(0xffffffffu, tmax_b, 1));
        tmax_b = fmaxf(tmax_b, __shfl_xor_sync(0xffffffffu, tmax_b, 2));

        float mn_a = fmaxf(m_a, tmax_a);
        float mn_b = fmaxf(m_b, tmax_b);
        float al_a = __expf(m_a - mn_a);
        float al_b = __expf(m_b - mn_b);
        m_a = mn_a; m_b = mn_b;

        __syncwarp();   // previous chunk's P reads done before overwrite

        float sum_a = 0.f, sum_b = 0.f;
        {
            int r0 = (lane >> 2);
            int cc = 2 * (lane & 3);
#pragma unroll
            for (int nt = 0; nt < 8; nt++) {
                float p0 = __expf(sacc[nt][0] - mn_a);
                float p1 = __expf(sacc[nt][1] - mn_a);
                float p2 = __expf(sacc[nt][2] - mn_b);
                float p3 = __expf(sacc[nt][3] - mn_b);
                sum_a += p0 + p1;
                sum_b += p2 + p3;
                int col = nt * 8 + cc;
                *(__half2*)(Pw + r0 * PS + col) =
                    __float22half2_rn(make_float2(p0, p1));
                *(__half2*)(Pw + (r0 + 8) * PS + col) =
                    __float22half2_rn(make_float2(p2, p3));
            }
        }
        sum_a += __shfl_xor_sync(0xffffffffu, sum_a, 1);
        sum_a += __shfl_xor_sync(0xffffffffu, sum_a, 2);
        sum_b += __shfl_xor_sync(0xffffffffu, sum_b, 1);
        sum_b += __shfl_xor_sync(0xffffffffu, sum_b, 2);
        l_a = l_a * al_a + sum_a;
        l_b = l_b * al_b + sum_b;

#pragma unroll
        for (int nt = 0; nt < 12; nt++) {
            oacc[nt][0] *= al_a; oacc[nt][1] *= al_a;
            oacc[nt][2] *= al_b; oacc[nt][3] *= al_b;
        }

        __syncwarp();   // P writes visible within warp

        // ---- O += P V ----
#pragma unroll
        for (int jj = 0; jj < 4; jj++) {
            uint32_t af[4];
            ldsm4(af, sPw + (((idx & 1) * 8 + lrow) * PS
                             + jj * 16 + (idx >> 1) * 8) * 2);
#pragma unroll
            for (int dt2 = 0; dt2 < 6; dt2++) {
                uint32_t r[4];
                ldsm4t(r, sVb + ((jj * 16 + (idx & 1) * 8 + lrow) * VS
                                 + dt2 * 16 + (idx >> 1) * 8) * 2);
                uint32_t b0[2] = {r[0], r[1]};
                uint32_t b1[2] = {r[2], r[3]};
                mma_f16(oacc[2 * dt2], af, b0);
                mma_f16(oacc[2 * dt2 + 1], af, b1);
            }
        }
    }

    float invla = 1.0f / l_a;
    float invlb = 1.0f / l_b;
    int row0 = quarter * 64 + wid * 16 + (lane >> 2);
    __half* o0 = g_oh + (size_t)(bf * SEQ + row0) * DMODEL + h * HEADDIM;
    __half* o1 = g_oh + (size_t)(bf * SEQ + row0 + 8) * DMODEL + h * HEADDIM;
#pragma unroll
    for (int nt = 0; nt < 12; nt++) {
        int col = nt * 8 + 2 * (lane & 3);
        *(__half2*)(o0 + col) = __float22half2_rn(
            make_float2(oacc[nt][0] * invla, oacc[nt][1] * invla));
        *(__half2*)(o1 + col) = __float22half2_rn(
            make_float2(oacc[nt][2] * invlb, oacc[nt][3] * invlb));
    }
}

// ============================================================================
// launch
// ============================================================================
extern "C" void kernel_launch(void* const* d_in, const int* in_sizes, int n_in,
                              void* d_out, int out_size)
{
    const float* x     = (const float*)d_in[0];
    const float* w_qkv = (const float*)d_in[1];
    const float* w_o   = (const float*)d_in[2];
    float* out = (float*)d_out;

    __half *xh_p, *wh_p, *qkvh_p, *oh_p;
    cudaGetSymbolAddress((void**)&xh_p, g_xh);
    cudaGetSymbolAddress((void**)&wh_p, g_wh);
    cudaGetSymbolAddress((void**)&qkvh_p, g_qkvh);
    cudaGetSymbolAddress((void**)&oh_p, g_oh);

    cudaFuncSetAttribute(gemm_f16<__half>,
                         cudaFuncAttributeMaxDynamicSharedMemorySize, GEMM_SMEM);
    cudaFuncSetAttribute(gemm_f16<float>,
                         cudaFuncAttributeMaxDynamicSharedMemorySize, GEMM_SMEM);
    cudaFuncSetAttribute(attn_kernel,
                         cudaFuncAttributeMaxDynamicSharedMemorySize, ATTN_SMEM);

    int n8;

    // convert x -> fp16, w_qkv -> fp16
    n8 = MTOK * DMODEL / 8;
    f32_to_f16_kernel<<<(n8 + 255) / 256, 256>>>((const float4*)x, (uint4*)xh_p, n8);
    n8 = QKV_N * DMODEL / 8;
    f32_to_f16_kernel<<<(n8 + 255) / 256, 256>>>((const float4*)w_qkv, (uint4*)wh_p, n8);

    // 1) QKV projection: qkvh[32768,1920] = xh @ w_qkv^T  (fp16 out)
    gemm_f16<__half><<<dim3(QKV_N / 128, MTOK / 256), 256, GEMM_SMEM>>>(
        xh_p, wh_p, qkvh_p, QKV_N, DMODEL);

    // 2) qk-norm + spatial RoPE + transpose (fp16 q/k/v)
    {
        int total_warps = MTOK * NHEADS + 2 * MTOK * NGROUPS;
        normrope_kernel<<<total_warps / 8, 256>>>(qkvh_p);
    }

    // 3) flash attention (fp16 mma, 2 CTAs/SM, double-buffered K/V)
    attn_kernel<<<dim3(4, NHEADS, BFRAMES), 128, ATTN_SMEM>>>();

    // convert w_o -> fp16
    n8 = DMODEL * DMODEL / 8;
    f32_to_f16_kernel<<<(n8 + 255) / 256, 256>>>((const float4*)w_o, (uint4*)wh_p, n8);

    // 4) output projection: out[32768,1152] = oh @ w_o^T  (fp32 out)
    gemm_f16<float><<<dim3(DMODEL / 128, MTOK / 256), 256, GEMM_SMEM>>>(
        oh_p, wh_p, out, DMODEL, DMODEL);
}

// round 11
// speedup vs baseline: 1.2008x; 1.1021x over previous
#include <cuda_runtime.h>
#include <cuda_fp16.h>
#include <math.h>
#include <stdint.h>

// ---------------- problem constants (fixed by setup_inputs) ----------------
#define BFRAMES   128          // B*T = 8*16
#define SEQ       256          // H*W = 16*16
#define DMODEL    1152
#define NHEADS    12
#define NGROUPS   4
#define HEADDIM   96
#define QKV_N     1920         // 12*96 + 2*4*96
#define MTOK      32768        // BFRAMES*SEQ
#define SM_SCALE  0.1020620726159658f   // 96^-0.5

// ---------------- scratch (device globals; no allocation allowed) ----------
__device__ __half g_xh[(size_t)MTOK * DMODEL];      // fp16 x
__device__ __half g_wh[(size_t)QKV_N * DMODEL];     // fp16 weights (reused)
__device__ __half g_qkvh[(size_t)MTOK * QKV_N];     // fp16 qkv
__device__ __half g_qh[(size_t)BFRAMES * NHEADS * SEQ * HEADDIM];
__device__ __half g_kh[(size_t)BFRAMES * NGROUPS * SEQ * HEADDIM];
__device__ __half g_vh[(size_t)BFRAMES * NGROUPS * SEQ * HEADDIM];
__device__ __half g_oh[(size_t)MTOK * DMODEL];      // fp16 attention output

// ============================================================================
// helpers
// ============================================================================
__device__ __forceinline__ uint32_t smem_u32(const void* p) {
    uint32_t a;
    asm("{ .reg .u64 t; cvta.to.shared.u64 t, %1; cvt.u32.u64 %0, t; }"
        : "=r"(a) : "l"(p));
    return a;
}

__device__ __forceinline__ void cp_async16(uint32_t saddr, const void* gptr) {
    asm volatile("cp.async.cg.shared.global [%0], [%1], 16;" :: "r"(saddr), "l"(gptr));
}

__device__ __forceinline__ void mma_f16(float c[4], const uint32_t a[4],
                                        const uint32_t b[2]) {
    asm volatile(
        "mma.sync.aligned.m16n8k16.row.col.f32.f16.f16.f32 "
        "{%0,%1,%2,%3}, {%4,%5,%6,%7}, {%8,%9}, {%0,%1,%2,%3};"
        : "+f"(c[0]), "+f"(c[1]), "+f"(c[2]), "+f"(c[3])
        : "r"(a[0]), "r"(a[1]), "r"(a[2]), "r"(a[3]), "r"(b[0]), "r"(b[1]));
}

__device__ __forceinline__ void ldsm4(uint32_t r[4], uint32_t addr) {
    asm volatile("ldmatrix.sync.aligned.m8n8.x4.shared.b16 {%0,%1,%2,%3}, [%4];"
                 : "=r"(r[0]), "=r"(r[1]), "=r"(r[2]), "=r"(r[3]) : "r"(addr));
}

__device__ __forceinline__ void ldsm4t(uint32_t r[4], uint32_t addr) {
    asm volatile("ldmatrix.sync.aligned.m8n8.x4.trans.shared.b16 {%0,%1,%2,%3}, [%4];"
                 : "=r"(r[0]), "=r"(r[1]), "=r"(r[2]), "=r"(r[3]) : "r"(addr));
}

// ============================================================================
// fp16 mma.sync GEMM (NT): C[M,N] = A[M,K] * B[N,K]^T, fp32 accumulate.
// NOW: 128-thread CTAs, 128x128 tile, 2 CTAs/SM (barrier/pipeline overlap).
// BK=64, 3-stage cp.async, single __syncthreads per iter, warp tile 64x64.
// Smem rows padded to 72 halves (144B) -> all LDSM phases conflict-free.
// ============================================================================
#define HSTR      72
#define STAGE_H   ((128 + 128) * HSTR)       // 18432 halves
#define GEMM_SMEM (3 * STAGE_H * 2)          // 110592 bytes (x2 CTAs = 221KB < 227KB)

template <typename OT>
__global__ __launch_bounds__(128, 2)
void gemm_f16(const __half* __restrict__ A, const __half* __restrict__ B,
              OT* __restrict__ C, int ldC, int K)
{
    extern __shared__ __half smh[];
    const int tid    = threadIdx.x;
    const int lane   = tid & 31;
    const int wid    = tid >> 5;         // 0..3
    const int warp_m = wid & 1;          // 2 warps over M (64 rows each)
    const int warp_n = wid >> 1;         // 2 warps over N (64 cols each)
    const int m0 = blockIdx.y * 128;
    const int n0 = blockIdx.x * 128;
    const int ITERS = K >> 6;            // BK = 64

    const __half* Ag = A + (size_t)m0 * K;
    const __half* Bg = B + (size_t)n0 * K;
    const uint32_t sbase = smem_u32(smh);

    auto load_stage = [&](int chunk, int st) {
        uint32_t abase = sbase + st * (STAGE_H * 2);
        uint32_t bbase = abase + 128 * (HSTR * 2);
        const __half* Ac = Ag + chunk * 64;
        const __half* Bc = Bg + chunk * 64;
#pragma unroll
        for (int j = 0; j < 8; j++) {            // A: 128 rows x 8 chunks of 16B
            int idx = tid + j * 128;
            int row = idx >> 3, c = idx & 7;
            cp_async16(abase + row * (HSTR * 2) + c * 16,
                       Ac + (size_t)row * K + c * 8);
        }
#pragma unroll
        for (int j = 0; j < 8; j++) {            // B: 128 rows x 8 chunks of 16B
            int idx = tid + j * 128;
            int row = idx >> 3, c = idx & 7;
            cp_async16(bbase + row * (HSTR * 2) + c * 16,
                       Bc + (size_t)row * K + c * 8);
        }
    };

    float acc[4][8][4];
#pragma unroll
    for (int mt = 0; mt < 4; mt++)
#pragma unroll
        for (int nt = 0; nt < 8; nt++)
#pragma unroll
            for (int r = 0; r < 4; r++) acc[mt][nt][r] = 0.f;

    const int arow = warp_m * 64 + (lane & 15);
    const int acol = (lane >> 4) * 8;
    const int brow = warp_n * 64 + (lane & 7) + (lane >> 4) * 8;
    const int bcol = ((lane >> 3) & 1) * 8;

    load_stage(0, 0);
    asm volatile("cp.async.commit_group;");
    if (ITERS > 1) load_stage(1, 1);
    asm volatile("cp.async.commit_group;");

    for (int i = 0; i < ITERS; i++) {
        asm volatile("cp.async.wait_group 1;");
        __syncthreads();

        if (i + 2 < ITERS) load_stage(i + 2, (i + 2) % 3);
        asm volatile("cp.async.commit_group;");

        const int st = i % 3;
        uint32_t abase = sbase + st * (STAGE_H * 2);
        uint32_t bbase = abase + 128 * (HSTR * 2);

#pragma unroll
        for (int kstep = 0; kstep < 4; kstep++) {
            uint32_t af[4][4];
#pragma unroll
            for (int mt = 0; mt < 4; mt++)
                ldsm4(af[mt], abase + ((arow + mt * 16) * HSTR
                                       + kstep * 16 + acol) * 2);
            uint32_t bf[8][2];
#pragma unroll
            for (int ntp = 0; ntp < 4; ntp++) {
                uint32_t r[4];
                ldsm4(r, bbase + ((brow + ntp * 16) * HSTR
                                  + kstep * 16 + bcol) * 2);
                bf[2 * ntp][0] = r[0]; bf[2 * ntp][1] = r[1];
                bf[2 * ntp + 1][0] = r[2]; bf[2 * ntp + 1][1] = r[3];
            }
#pragma unroll
            for (int mt = 0; mt < 4; mt++)
#pragma unroll
                for (int nt = 0; nt < 8; nt++)
                    mma_f16(acc[mt][nt], af[mt], bf[nt]);
        }
    }

#pragma unroll
    for (int mt = 0; mt < 4; mt++) {
        int row0 = m0 + warp_m * 64 + mt * 16 + (lane >> 2);
#pragma unroll
        for (int nt = 0; nt < 8; nt++) {
            int col = n0 + warp_n * 64 + nt * 8 + (lane & 3) * 2;
            if constexpr (sizeof(OT) == 4) {
                *(float2*)((float*)C + (size_t)row0 * ldC + col) =
                    make_float2(acc[mt][nt][0], acc[mt][nt][1]);
                *(float2*)((float*)C + (size_t)(row0 + 8) * ldC + col) =
                    make_float2(acc[mt][nt][2], acc[mt][nt][3]);
            } else {
                *(__half2*)((__half*)C + (size_t)row0 * ldC + col) =
                    __float22half2_rn(make_float2(acc[mt][nt][0], acc[mt][nt][1]));
                *(__half2*)((__half*)C + (size_t)(row0 + 8) * ldC + col) =
                    __float22half2_rn(make_float2(acc[mt][nt][2], acc[mt][nt][3]));
            }
        }
    }
}

// ============================================================================
// convert fp32 -> fp16 (RN), 8 elems per thread
// ============================================================================
__global__ __launch_bounds__(256) void f32_to_f16_kernel(
    const float4* __restrict__ in, uint4* __restrict__ out, int n8)
{
    int i = blockIdx.x * blockDim.x + threadIdx.x;
    if (i >= n8) return;
    float4 a = in[2 * i], b = in[2 * i + 1];
    __half2 h0 = __float22half2_rn(make_float2(a.x, a.y));
    __half2 h1 = __float22half2_rn(make_float2(a.z, a.w));
    __half2 h2 = __float22half2_rn(make_float2(b.x, b.y));
    __half2 h3 = __float22half2_rn(make_float2(b.z, b.w));
    uint4 o;
    o.x = *(uint32_t*)&h0; o.y = *(uint32_t*)&h1;
    o.z = *(uint32_t*)&h2; o.w = *(uint32_t*)&h3;
    out[i] = o;
}

// ============================================================================
// norm + RoPE + layout transpose; fp16 in, fp16 out (math in fp32) (R10-proven)
// ============================================================================
__global__ __launch_bounds__(256) void normrope_kernel(const __half* __restrict__ qkv)
{
    const int NQv = MTOK * NHEADS;
    const int NKv = MTOK * NGROUPS;
    int wid  = (blockIdx.x * blockDim.x + threadIdx.x) >> 5;
    int lane = threadIdx.x & 31;
    if (wid >= NQv + 2 * NKv) return;

    const __half* src;
    __half* dst;
    int t;
    bool do_norm_rope = true;

    if (wid < NQv) {
        t = wid / NHEADS; int h = wid % NHEADS;
        src = qkv + (size_t)t * QKV_N + h * HEADDIM;
        int bf = t >> 8, s = t & 255;
        dst = g_qh + ((size_t)(bf * NHEADS + h) * SEQ + s) * HEADDIM;
    } else if (wid < NQv + NKv) {
        int v = wid - NQv; t = v / NGROUPS; int g = v % NGROUPS;
        src = qkv + (size_t)t * QKV_N + DMODEL + g * HEADDIM;
        int bf = t >> 8, s = t & 255;
        dst = g_kh + ((size_t)(bf * NGROUPS + g) * SEQ + s) * HEADDIM;
    } else {
        int v = wid - NQv - NKv; t = v / NGROUPS; int g = v % NGROUPS;
        src = qkv + (size_t)t * QKV_N + DMODEL + NGROUPS * HEADDIM + g * HEADDIM;
        int bf = t >> 8, s = t & 255;
        dst = g_vh + ((size_t)(bf * NGROUPS + g) * SEQ + s) * HEADDIM;
        do_norm_rope = false;
    }

    float x0 = __half2float(src[lane]);
    float x1 = __half2float(src[lane + 32]);
    float x2 = __half2float(src[lane + 64]);

    if (do_norm_rope) {
        float ss = fmaf(x0, x0, fmaf(x1, x1, x2 * x2));
#pragma unroll
        for (int o = 16; o; o >>= 1) ss += __shfl_xor_sync(0xffffffffu, ss, o);
        float inv = 1.0f / fmaxf(sqrtf(ss), 1e-10f);
        x0 *= inv; x1 *= inv; x2 *= inv;

        int s = t & 255;
        float pos = (float)((s >> 4) + (s & 15));
        int i = lane & 15;
        float a = __shfl_sync(0xffffffffu, x0, 2 * i);
        float b = __shfl_sync(0xffffffffu, x0, 2 * i + 1);
        float invf = exp2f(-(float)i * 0.8304820237218406f);
        float ang = pos * invf;
        float sn, cs;
        __sincosf(ang, &sn, &cs);
        x0 = (lane < 16) ? fmaf(a, cs, -b * sn) : fmaf(a, sn, b * cs);
    }

    dst[lane]      = __float2half_rn(x0);
    dst[lane + 32] = __float2half_rn(x1);
    dst[lane + 64] = __float2half_rn(x2);
}

// ============================================================================
// Flash attention, fp16 mma.sync m16n8k16, fp32 accum/softmax. (R10-proven)
// 128-thread CTAs (4 warps, 64 q-rows), 2 CTAs/SM, double-buffered K/V.
// ============================================================================
#define KS 104
#define VS 104
#define PS 72
#define KV_STG   (64 * (KS + VS))                       // halves per stage
#define ATTN_SMEM ((2 * KV_STG + 64 * PS) * 2)          // 62464 bytes

__global__ __launch_bounds__(128, 2) void attn_kernel()
{
    extern __shared__ __half smh[];
    const uint32_t sbase = smem_u32(smh);

    const int tid  = threadIdx.x;
    const int lane = tid & 31;
    const int wid  = tid >> 5;          // 0..3
    const int quarter = blockIdx.x;     // 0..3 (64 q-rows each)
    const int h    = blockIdx.y;
    const int bf   = blockIdx.z;
    const int g    = h / 3;

    const __half* Qg = g_qh + ((size_t)(bf * NHEADS + h) * SEQ
                               + quarter * 64 + wid * 16) * HEADDIM;
    const __half* Kg = g_kh + (size_t)(bf * NGROUPS + g) * SEQ * HEADDIM;
    const __half* Vg = g_vh + (size_t)(bf * NGROUPS + g) * SEQ * HEADDIM;

    uint32_t qf[6][4];
    {
        const __half* q0 = Qg + (lane >> 2) * HEADDIM;
        const __half* q1 = Qg + ((lane >> 2) + 8) * HEADDIM;
        int cc = 2 * (lane & 3);
#pragma unroll
        for (int j = 0; j < 6; j++) {
            qf[j][0] = *(const uint32_t*)(q0 + j * 16 + cc);
            qf[j][1] = *(const uint32_t*)(q1 + j * 16 + cc);
            qf[j][2] = *(const uint32_t*)(q0 + j * 16 + 8 + cc);
            qf[j][3] = *(const uint32_t*)(q1 + j * 16 + 8 + cc);
        }
    }

    const uint32_t sPw = sbase + (2 * KV_STG + wid * 16 * PS) * 2;
    __half* Pw = smh + 2 * KV_STG + wid * 16 * PS;

    const int idx  = lane >> 3;
    const int lrow = lane & 7;

    auto load_kv = [&](int kt, int st) {
        uint32_t kb = sbase + st * (KV_STG * 2);
        uint32_t vb = kb + 64 * KS * 2;
        const __half* Kc = Kg + (size_t)kt * 64 * HEADDIM;
        const __half* Vc = Vg + (size_t)kt * 64 * HEADDIM;
#pragma unroll
        for (int it = 0; it < 6; it++) {
            int i = tid + it * 128;
            int r = i / 12, c = (i % 12) * 8;
            cp_async16(kb + (r * KS + c) * 2, Kc + r * HEADDIM + c);
            cp_async16(vb + (r * VS + c) * 2, Vc + r * HEADDIM + c);
        }
    };

    float m_a = -INFINITY, m_b = -INFINITY;
    float l_a = 0.f, l_b = 0.f;
    float oacc[12][4];
#pragma unroll
    for (int nt = 0; nt < 12; nt++)
#pragma unroll
        for (int r = 0; r < 4; r++) oacc[nt][r] = 0.f;

    load_kv(0, 0);
    asm volatile("cp.async.commit_group;");

    for (int kt = 0; kt < 4; kt++) {
        __syncthreads();
        if (kt < 3) {
            load_kv(kt + 1, (kt + 1) & 1);
            asm volatile("cp.async.commit_group;");
            asm volatile("cp.async.wait_group 1;");
        } else {
            asm volatile("cp.async.wait_group 0;");
        }
        __syncthreads();

        const int st = kt & 1;
        const uint32_t sKb = sbase + st * (KV_STG * 2);
        const uint32_t sVb = sKb + 64 * KS * 2;

        // ---- S = Q K^T ----
        float sacc[8][4];
#pragma unroll
        for (int nt = 0; nt < 8; nt++)
#pragma unroll
            for (int r = 0; r < 4; r++) sacc[nt][r] = 0.f;

#pragma unroll
        for (int j = 0; j < 6; j++) {
#pragma unroll
            for (int nt2 = 0; nt2 < 4; nt2++) {
                uint32_t r[4];
                ldsm4(r, sKb + ((nt2 * 16 + (idx >> 1) * 8 + lrow) * KS
                                + j * 16 + (idx & 1) * 8) * 2);
                uint32_t b0[2] = {r[0], r[1]};
                uint32_t b1[2] = {r[2], r[3]};
                mma_f16(sacc[2 * nt2], qf[j], b0);
                mma_f16(sacc[2 * nt2 + 1], qf[j], b1);
            }
        }

        // ---- online softmax ----
        float tmax_a = -INFINITY, tmax_b = -INFINITY;
#pragma unroll
        for (int nt = 0; nt < 8; nt++) {
#pragma unroll
            for (int r = 0; r < 4; r++) sacc[nt][r] *= SM_SCALE;
            tmax_a = fmaxf(tmax_a, fmaxf(sacc[nt][0], sacc[nt][1]));
            tmax_b = fmaxf(tmax_b, fmaxf(sacc[nt][2], sacc[nt][3]));
        }
        tmax_a = fmaxf(tmax_a, __shfl_xor_sync(0xffffffffu, tmax_a, 1));
        tmax_a = fmaxf(tmax_a, __shfl_xor_sync(0xffffffffu, tmax_a, 2));
        tmax_b = fmaxf(tmax_b, __shfl_xor_sync(0xffffffffu, tmax_b, 1));
        tmax_b = fmaxf(tmax_b, __shfl_xor_sync(0xffffffffu, tmax_b, 2));

        float mn_a = fmaxf(m_a, tmax_a);
        float mn_b = fmaxf(m_b, tmax_b);
        float al_a = __expf(m_a - mn_a);
        float al_b = __expf(m_b - mn_b);
        m_a = mn_a; m_b = mn_b;

        __syncwarp();

        float sum_a = 0.f, sum_b = 0.f;
        {
            int r0 = (lane >> 2);
            int cc = 2 * (lane & 3);
#pragma unroll
            for (int nt = 0; nt < 8; nt++) {
                float p0 = __expf(sacc[nt][0] - mn_a);
                float p1 = __expf(sacc[nt][1] - mn_a);
                float p2 = __expf(sacc[nt][2] - mn_b);
                float p3 = __expf(sacc[nt][3] - mn_b);
                sum_a += p0 + p1;
                sum_b += p2 + p3;
                int col = nt * 8 + cc;
                *(__half2*)(Pw + r0 * PS + col) =
                    __float22half2_rn(make_float2(p0, p1));
                *(__half2*)(Pw + (r0 + 8) * PS + col) =
                    __float22half2_rn(make_float2(p2, p3));
            }
        }
        sum_a += __shfl_xor_sync(0xffffffffu, sum_a, 1);
        sum_a += __shfl_xor_sync(0xffffffffu, sum_a, 2);
        sum_b += __shfl_xor_sync(0xffffffffu, sum_b, 1);
        sum_b += __shfl_xor_sync(0xffffffffu, sum_b, 2);
        l_a = l_a * al_a + sum_a;
        l_b = l_b * al_b + sum_b;

#pragma unroll
        for (int nt = 0; nt < 12; nt++) {
            oacc[nt][0] *= al_a; oacc[nt][1] *= al_a;
            oacc[nt][2] *= al_b; oacc[nt][3] *= al_b;
        }

        __syncwarp();

        // ---- O += P V ----
#pragma unroll
        for (int jj = 0; jj < 4; jj++) {
            uint32_t af[4];
            ldsm4(af, sPw + (((idx & 1) * 8 + lrow) * PS
                             + jj * 16 + (idx >> 1) * 8) * 2);
#pragma unroll
            for (int dt2 = 0; dt2 < 6; dt2++) {
                uint32_t r[4];
                ldsm4t(r, sVb + ((jj * 16 + (idx & 1) * 8 + lrow) * VS
                                 + dt2 * 16 + (idx >> 1) * 8) * 2);
                uint32_t b0[2] = {r[0], r[1]};
                uint32_t b1[2] = {r[2], r[3]};
                mma_f16(oacc[2 * dt2], af, b0);
                mma_f16(oacc[2 * dt2 + 1], af, b1);
            }
        }
    }

    float invla = 1.0f / l_a;
    float invlb = 1.0f / l_b;
    int row0 = quarter * 64 + wid * 16 + (lane >> 2);
    __half* o0 = g_oh + (size_t)(bf * SEQ + row0) * DMODEL + h * HEADDIM;
    __half* o1 = g_oh + (size_t)(bf * SEQ + row0 + 8) * DMODEL + h * HEADDIM;
#pragma unroll
    for (int nt = 0; nt < 12; nt++) {
        int col = nt * 8 + 2 * (lane & 3);
        *(__half2*)(o0 + col) = __float22half2_rn(
            make_float2(oacc[nt][0] * invla, oacc[nt][1] * invla));
        *(__half2*)(o1 + col) = __float22half2_rn(
            make_float2(oacc[nt][2] * invlb, oacc[nt][3] * invlb));
    }
}

// ============================================================================
// launch
// ============================================================================
extern "C" void kernel_launch(void* const* d_in, const int* in_sizes, int n_in,
                              void* d_out, int out_size)
{
    const float* x     = (const float*)d_in[0];
    const float* w_qkv = (const float*)d_in[1];
    const float* w_o   = (const float*)d_in[2];
    float* out = (float*)d_out;

    __half *xh_p, *wh_p, *qkvh_p, *oh_p;
    cudaGetSymbolAddress((void**)&xh_p, g_xh);
    cudaGetSymbolAddress((void**)&wh_p, g_wh);
    cudaGetSymbolAddress((void**)&qkvh_p, g_qkvh);
    cudaGetSymbolAddress((void**)&oh_p, g_oh);

    cudaFuncSetAttribute(gemm_f16<__half>,
                         cudaFuncAttributeMaxDynamicSharedMemorySize, GEMM_SMEM);
    cudaFuncSetAttribute(gemm_f16<float>,
                         cudaFuncAttributeMaxDynamicSharedMemorySize, GEMM_SMEM);
    cudaFuncSetAttribute(attn_kernel,
                         cudaFuncAttributeMaxDynamicSharedMemorySize, ATTN_SMEM);

    int n8;

    // convert x -> fp16, w_qkv -> fp16
    n8 = MTOK * DMODEL / 8;
    f32_to_f16_kernel<<<(n8 + 255) / 256, 256>>>((const float4*)x, (uint4*)xh_p, n8);
    n8 = QKV_N * DMODEL / 8;
    f32_to_f16_kernel<<<(n8 + 255) / 256, 256>>>((const float4*)w_qkv, (uint4*)wh_p, n8);

    // 1) QKV projection: qkvh[32768,1920] = xh @ w_qkv^T  (fp16 out, 2 CTAs/SM)
    gemm_f16<__half><<<dim3(QKV_N / 128, MTOK / 128), 128, GEMM_SMEM>>>(
        xh_p, wh_p, qkvh_p, QKV_N, DMODEL);

    // 2) qk-norm + spatial RoPE + transpose (fp16 q/k/v)
    {
        int total_warps = MTOK * NHEADS + 2 * MTOK * NGROUPS;
        normrope_kernel<<<total_warps / 8, 256>>>(qkvh_p);
    }

    // 3) flash attention (fp16 mma, 2 CTAs/SM, double-buffered K/V)
    attn_kernel<<<dim3(4, NHEADS, BFRAMES), 128, ATTN_SMEM>>>();

    // convert w_o -> fp16
    n8 = DMODEL * DMODEL / 8;
    f32_to_f16_kernel<<<(n8 + 255) / 256, 256>>>((const float4*)w_o, (uint4*)wh_p, n8);

    // 4) output projection: out[32768,1152] = oh @ w_o^T  (fp32 out, 2 CTAs/SM)
    gemm_f16<float><<<dim3(DMODEL / 128, MTOK / 128), 128, GEMM_SMEM>>>(
        oh_p, wh_p, out, DMODEL, DMODEL);
}

// round 12
// speedup vs baseline: 1.2031x; 1.0019x over previous
#include <cuda_runtime.h>
#include <cuda_fp16.h>
#include <math.h>
#include <stdint.h>

// ---------------- problem constants (fixed by setup_inputs) ----------------
#define BFRAMES   128          // B*T = 8*16
#define SEQ       256          // H*W = 16*16
#define DMODEL    1152
#define NHEADS    12
#define NGROUPS   4
#define HEADDIM   96
#define QKV_N     1920         // 12*96 + 2*4*96
#define MTOK      32768        // BFRAMES*SEQ
#define SM_SCALE  0.1020620726159658f   // 96^-0.5

// ---------------- scratch (device globals; no allocation allowed) ----------
__device__ __half g_xh[(size_t)MTOK * DMODEL];      // fp16 x
__device__ __half g_wh[(size_t)QKV_N * DMODEL];     // fp16 weights (reused)
__device__ __half g_qkvh[(size_t)MTOK * QKV_N];     // fp16 qkv
__device__ __half g_qh[(size_t)BFRAMES * NHEADS * SEQ * HEADDIM];
__device__ __half g_kh[(size_t)BFRAMES * NGROUPS * SEQ * HEADDIM];
__device__ __half g_vh[(size_t)BFRAMES * NGROUPS * SEQ * HEADDIM];
__device__ __half g_oh[(size_t)MTOK * DMODEL];      // fp16 attention output

// ============================================================================
// helpers
// ============================================================================
__device__ __forceinline__ uint32_t smem_u32(const void* p) {
    uint32_t a;
    asm("{ .reg .u64 t; cvta.to.shared.u64 t, %1; cvt.u32.u64 %0, t; }"
        : "=r"(a) : "l"(p));
    return a;
}

__device__ __forceinline__ void cp_async16(uint32_t saddr, const void* gptr) {
    asm volatile("cp.async.cg.shared.global [%0], [%1], 16;" :: "r"(saddr), "l"(gptr));
}

__device__ __forceinline__ void mma_f16(float c[4], const uint32_t a[4],
                                        const uint32_t b[2]) {
    asm volatile(
        "mma.sync.aligned.m16n8k16.row.col.f32.f16.f16.f32 "
        "{%0,%1,%2,%3}, {%4,%5,%6,%7}, {%8,%9}, {%0,%1,%2,%3};"
        : "+f"(c[0]), "+f"(c[1]), "+f"(c[2]), "+f"(c[3])
        : "r"(a[0]), "r"(a[1]), "r"(a[2]), "r"(a[3]), "r"(b[0]), "r"(b[1]));
}

__device__ __forceinline__ void ldsm4(uint32_t r[4], uint32_t addr) {
    asm volatile("ldmatrix.sync.aligned.m8n8.x4.shared.b16 {%0,%1,%2,%3}, [%4];"
                 : "=r"(r[0]), "=r"(r[1]), "=r"(r[2]), "=r"(r[3]) : "r"(addr));
}

__device__ __forceinline__ void ldsm4t(uint32_t r[4], uint32_t addr) {
    asm volatile("ldmatrix.sync.aligned.m8n8.x4.trans.shared.b16 {%0,%1,%2,%3}, [%4];"
                 : "=r"(r[0]), "=r"(r[1]), "=r"(r[2]), "=r"(r[3]) : "r"(addr));
}

// ============================================================================
// fp16 mma.sync GEMM (NT): C[M,N] = A[M,K] * B[N,K]^T, fp32 accumulate.
// 128-thread CTAs, 128x128 tile, 2 CTAs/SM. BK=64, 3-stage cp.async,
// single __syncthreads per iter, warp tile 64x64.
// NEW: register double-buffered ldmatrix fragments (prefetch kstep+1).
// ============================================================================
#define HSTR      72
#define STAGE_H   ((128 + 128) * HSTR)       // 18432 halves
#define GEMM_SMEM (3 * STAGE_H * 2)          // 110592 bytes (x2 CTAs = 221KB < 227KB)

template <typename OT>
__global__ __launch_bounds__(128, 2)
void gemm_f16(const __half* __restrict__ A, const __half* __restrict__ B,
              OT* __restrict__ C, int ldC, int K)
{
    extern __shared__ __half smh[];
    const int tid    = threadIdx.x;
    const int lane   = tid & 31;
    const int wid    = tid >> 5;         // 0..3
    const int warp_m = wid & 1;          // 2 warps over M (64 rows each)
    const int warp_n = wid >> 1;         // 2 warps over N (64 cols each)
    const int m0 = blockIdx.y * 128;
    const int n0 = blockIdx.x * 128;
    const int ITERS = K >> 6;            // BK = 64

    const __half* Ag = A + (size_t)m0 * K;
    const __half* Bg = B + (size_t)n0 * K;
    const uint32_t sbase = smem_u32(smh);

    auto load_stage = [&](int chunk, int st) {
        uint32_t abase = sbase + st * (STAGE_H * 2);
        uint32_t bbase = abase + 128 * (HSTR * 2);
        const __half* Ac = Ag + chunk * 64;
        const __half* Bc = Bg + chunk * 64;
#pragma unroll
        for (int j = 0; j < 8; j++) {            // A: 128 rows x 8 chunks of 16B
            int idx = tid + j * 128;
            int row = idx >> 3, c = idx & 7;
            cp_async16(abase + row * (HSTR * 2) + c * 16,
                       Ac + (size_t)row * K + c * 8);
        }
#pragma unroll
        for (int j = 0; j < 8; j++) {            // B: 128 rows x 8 chunks of 16B
            int idx = tid + j * 128;
            int row = idx >> 3, c = idx & 7;
            cp_async16(bbase + row * (HSTR * 2) + c * 16,
                       Bc + (size_t)row * K + c * 8);
        }
    };

    float acc[4][8][4];
#pragma unroll
    for (int mt = 0; mt < 4; mt++)
#pragma unroll
        for (int nt = 0; nt < 8; nt++)
#pragma unroll
            for (int r = 0; r < 4; r++) acc[mt][nt][r] = 0.f;

    const int arow = warp_m * 64 + (lane & 15);
    const int acol = (lane >> 4) * 8;
    const int brow = warp_n * 64 + (lane & 7) + (lane >> 4) * 8;
    const int bcol = ((lane >> 3) & 1) * 8;

    load_stage(0, 0);
    asm volatile("cp.async.commit_group;");
    if (ITERS > 1) load_stage(1, 1);
    asm volatile("cp.async.commit_group;");

    for (int i = 0; i < ITERS; i++) {
        asm volatile("cp.async.wait_group 1;");
        __syncthreads();

        if (i + 2 < ITERS) load_stage(i + 2, (i + 2) % 3);
        asm volatile("cp.async.commit_group;");

        const int st = i % 3;
        uint32_t abase = sbase + st * (STAGE_H * 2);
        uint32_t bbase = abase + 128 * (HSTR * 2);

        // fragment loader for one kstep into the given buffers
        auto load_frags = [&](int kstep, uint32_t af[4][4], uint32_t bf[8][2]) {
#pragma unroll
            for (int mt = 0; mt < 4; mt++)
                ldsm4(af[mt], abase + ((arow + mt * 16) * HSTR
                                       + kstep * 16 + acol) * 2);
#pragma unroll
            for (int ntp = 0; ntp < 4; ntp++) {
                uint32_t r[4];
                ldsm4(r, bbase + ((brow + ntp * 16) * HSTR
                                  + kstep * 16 + bcol) * 2);
                bf[2 * ntp][0] = r[0]; bf[2 * ntp][1] = r[1];
                bf[2 * ntp + 1][0] = r[2]; bf[2 * ntp + 1][1] = r[3];
            }
        };

        uint32_t af[2][4][4];
        uint32_t bf[2][8][2];
        load_frags(0, af[0], bf[0]);

#pragma unroll
        for (int kstep = 0; kstep < 4; kstep++) {
            const int cur = kstep & 1;
            const int nxt = cur ^ 1;
            if (kstep < 3) load_frags(kstep + 1, af[nxt], bf[nxt]);
#pragma unroll
            for (int mt = 0; mt < 4; mt++)
#pragma unroll
                for (int nt = 0; nt < 8; nt++)
                    mma_f16(acc[mt][nt], af[cur][mt], bf[cur][nt]);
        }
    }

#pragma unroll
    for (int mt = 0; mt < 4; mt++) {
        int row0 = m0 + warp_m * 64 + mt * 16 + (lane >> 2);
#pragma unroll
        for (int nt = 0; nt < 8; nt++) {
            int col = n0 + warp_n * 64 + nt * 8 + (lane & 3) * 2;
            if constexpr (sizeof(OT) == 4) {
                *(float2*)((float*)C + (size_t)row0 * ldC + col) =
                    make_float2(acc[mt][nt][0], acc[mt][nt][1]);
                *(float2*)((float*)C + (size_t)(row0 + 8) * ldC + col) =
                    make_float2(acc[mt][nt][2], acc[mt][nt][3]);
            } else {
                *(__half2*)((__half*)C + (size_t)row0 * ldC + col) =
                    __float22half2_rn(make_float2(acc[mt][nt][0], acc[mt][nt][1]));
                *(__half2*)((__half*)C + (size_t)(row0 + 8) * ldC + col) =
                    __float22half2_rn(make_float2(acc[mt][nt][2], acc[mt][nt][3]));
            }
        }
    }
}

// ============================================================================
// convert fp32 -> fp16 (RN), 8 elems per thread
// ============================================================================
__global__ __launch_bounds__(256) void f32_to_f16_kernel(
    const float4* __restrict__ in, uint4* __restrict__ out, int n8)
{
    int i = blockIdx.x * blockDim.x + threadIdx.x;
    if (i >= n8) return;
    float4 a = in[2 * i], b = in[2 * i + 1];
    __half2 h0 = __float22half2_rn(make_float2(a.x, a.y));
    __half2 h1 = __float22half2_rn(make_float2(a.z, a.w));
    __half2 h2 = __float22half2_rn(make_float2(b.x, b.y));
    __half2 h3 = __float22half2_rn(make_float2(b.z, b.w));
    uint4 o;
    o.x = *(uint32_t*)&h0; o.y = *(uint32_t*)&h1;
    o.z = *(uint32_t*)&h2; o.w = *(uint32_t*)&h3;
    out[i] = o;
}

// ============================================================================
// norm + RoPE + layout transpose; fp16 in, fp16 out (math in fp32) (R10-proven)
// ============================================================================
__global__ __launch_bounds__(256) void normrope_kernel(const __half* __restrict__ qkv)
{
    const int NQv = MTOK * NHEADS;
    const int NKv = MTOK * NGROUPS;
    int wid  = (blockIdx.x * blockDim.x + threadIdx.x) >> 5;
    int lane = threadIdx.x & 31;
    if (wid >= NQv + 2 * NKv) return;

    const __half* src;
    __half* dst;
    int t;
    bool do_norm_rope = true;

    if (wid < NQv) {
        t = wid / NHEADS; int h = wid % NHEADS;
        src = qkv + (size_t)t * QKV_N + h * HEADDIM;
        int bf = t >> 8, s = t & 255;
        dst = g_qh + ((size_t)(bf * NHEADS + h) * SEQ + s) * HEADDIM;
    } else if (wid < NQv + NKv) {
        int v = wid - NQv; t = v / NGROUPS; int g = v % NGROUPS;
        src = qkv + (size_t)t * QKV_N + DMODEL + g * HEADDIM;
        int bf = t >> 8, s = t & 255;
        dst = g_kh + ((size_t)(bf * NGROUPS + g) * SEQ + s) * HEADDIM;
    } else {
        int v = wid - NQv - NKv; t = v / NGROUPS; int g = v % NGROUPS;
        src = qkv + (size_t)t * QKV_N + DMODEL + NGROUPS * HEADDIM + g * HEADDIM;
        int bf = t >> 8, s = t & 255;
        dst = g_vh + ((size_t)(bf * NGROUPS + g) * SEQ + s) * HEADDIM;
        do_norm_rope = false;
    }

    float x0 = __half2float(src[lane]);
    float x1 = __half2float(src[lane + 32]);
    float x2 = __half2float(src[lane + 64]);

    if (do_norm_rope) {
        float ss = fmaf(x0, x0, fmaf(x1, x1, x2 * x2));
#pragma unroll
        for (int o = 16; o; o >>= 1) ss += __shfl_xor_sync(0xffffffffu, ss, o);
        float inv = 1.0f / fmaxf(sqrtf(ss), 1e-10f);
        x0 *= inv; x1 *= inv; x2 *= inv;

        int s = t & 255;
        float pos = (float)((s >> 4) + (s & 15));
        int i = lane & 15;
        float a = __shfl_sync(0xffffffffu, x0, 2 * i);
        float b = __shfl_sync(0xffffffffu, x0, 2 * i + 1);
        float invf = exp2f(-(float)i * 0.8304820237218406f);
        float ang = pos * invf;
        float sn, cs;
        __sincosf(ang, &sn, &cs);
        x0 = (lane < 16) ? fmaf(a, cs, -b * sn) : fmaf(a, sn, b * cs);
    }

    dst[lane]      = __float2half_rn(x0);
    dst[lane + 32] = __float2half_rn(x1);
    dst[lane + 64] = __float2half_rn(x2);
}

// ============================================================================
// Flash attention, fp16 mma.sync m16n8k16, fp32 accum/softmax. (R10-proven)
// 128-thread CTAs (4 warps, 64 q-rows), 2 CTAs/SM, double-buffered K/V.
// ============================================================================
#define KS 104
#define VS 104
#define PS 72
#define KV_STG   (64 * (KS + VS))                       // halves per stage
#define ATTN_SMEM ((2 * KV_STG + 64 * PS) * 2)          // 62464 bytes

__global__ __launch_bounds__(128, 2) void attn_kernel()
{
    extern __shared__ __half smh[];
    const uint32_t sbase = smem_u32(smh);

    const int tid  = threadIdx.x;
    const int lane = tid & 31;
    const int wid  = tid >> 5;          // 0..3
    const int quarter = blockIdx.x;     // 0..3 (64 q-rows each)
    const int h    = blockIdx.y;
    const int bf   = blockIdx.z;
    const int g    = h / 3;

    const __half* Qg = g_qh + ((size_t)(bf * NHEADS + h) * SEQ
                               + quarter * 64 + wid * 16) * HEADDIM;
    const __half* Kg = g_kh + (size_t)(bf * NGROUPS + g) * SEQ * HEADDIM;
    const __half* Vg = g_vh + (size_t)(bf * NGROUPS + g) * SEQ * HEADDIM;

    uint32_t qf[6][4];
    {
        const __half* q0 = Qg + (lane >> 2) * HEADDIM;
        const __half* q1 = Qg + ((lane >> 2) + 8) * HEADDIM;
        int cc = 2 * (lane & 3);
#pragma unroll
        for (int j = 0; j < 6; j++) {
            qf[j][0] = *(const uint32_t*)(q0 + j * 16 + cc);
            qf[j][1] = *(const uint32_t*)(q1 + j * 16 + cc);
            qf[j][2] = *(const uint32_t*)(q0 + j * 16 + 8 + cc);
            qf[j][3] = *(const uint32_t*)(q1 + j * 16 + 8 + cc);
        }
    }

    const uint32_t sPw = sbase + (2 * KV_STG + wid * 16 * PS) * 2;
    __half* Pw = smh + 2 * KV_STG + wid * 16 * PS;

    const int idx  = lane >> 3;
    const int lrow = lane & 7;

    auto load_kv = [&](int kt, int st) {
        uint32_t kb = sbase + st * (KV_STG * 2);
        uint32_t vb = kb + 64 * KS * 2;
        const __half* Kc = Kg + (size_t)kt * 64 * HEADDIM;
        const __half* Vc = Vg + (size_t)kt * 64 * HEADDIM;
#pragma unroll
        for (int it = 0; it < 6; it++) {
            int i = tid + it * 128;
            int r = i / 12, c = (i % 12) * 8;
            cp_async16(kb + (r * KS + c) * 2, Kc + r * HEADDIM + c);
            cp_async16(vb + (r * VS + c) * 2, Vc + r * HEADDIM + c);
        }
    };

    float m_a = -INFINITY, m_b = -INFINITY;
    float l_a = 0.f, l_b = 0.f;
    float oacc[12][4];
#pragma unroll
    for (int nt = 0; nt < 12; nt++)
#pragma unroll
        for (int r = 0; r < 4; r++) oacc[nt][r] = 0.f;

    load_kv(0, 0);
    asm volatile("cp.async.commit_group;");

    for (int kt = 0; kt < 4; kt++) {
        __syncthreads();
        if (kt < 3) {
            load_kv(kt + 1, (kt + 1) & 1);
            asm volatile("cp.async.commit_group;");
            asm volatile("cp.async.wait_group 1;");
        } else {
            asm volatile("cp.async.wait_group 0;");
        }
        __syncthreads();

        const int st = kt & 1;
        const uint32_t sKb = sbase + st * (KV_STG * 2);
        const uint32_t sVb = sKb + 64 * KS * 2;

        // ---- S = Q K^T ----
        float sacc[8][4];
#pragma unroll
        for (int nt = 0; nt < 8; nt++)
#pragma unroll
            for (int r = 0; r < 4; r++) sacc[nt][r] = 0.f;

#pragma unroll
        for (int j = 0; j < 6; j++) {
#pragma unroll
            for (int nt2 = 0; nt2 < 4; nt2++) {
                uint32_t r[4];
                ldsm4(r, sKb + ((nt2 * 16 + (idx >> 1) * 8 + lrow) * KS
                                + j * 16 + (idx & 1) * 8) * 2);
                uint32_t b0[2] = {r[0], r[1]};
                uint32_t b1[2] = {r[2], r[3]};
                mma_f16(sacc[2 * nt2], qf[j], b0);
                mma_f16(sacc[2 * nt2 + 1], qf[j], b1);
            }
        }

        // ---- online softmax ----
        float tmax_a = -INFINITY, tmax_b = -INFINITY;
#pragma unroll
        for (int nt = 0; nt < 8; nt++) {
#pragma unroll
            for (int r = 0; r < 4; r++) sacc[nt][r] *= SM_SCALE;
            tmax_a = fmaxf(tmax_a, fmaxf(sacc[nt][0], sacc[nt][1]));
            tmax_b = fmaxf(tmax_b, fmaxf(sacc[nt][2], sacc[nt][3]));
        }
        tmax_a = fmaxf(tmax_a, __shfl_xor_sync(0xffffffffu, tmax_a, 1));
        tmax_a = fmaxf(tmax_a, __shfl_xor_sync(0xffffffffu, tmax_a, 2));
        tmax_b = fmaxf(tmax_b, __shfl_xor_sync(0xffffffffu, tmax_b, 1));
        tmax_b = fmaxf(tmax_b, __shfl_xor_sync(0xffffffffu, tmax_b, 2));

        float mn_a = fmaxf(m_a, tmax_a);
        float mn_b = fmaxf(m_b, tmax_b);
        float al_a = __expf(m_a - mn_a);
        float al_b = __expf(m_b - mn_b);
        m_a = mn_a; m_b = mn_b;

        __syncwarp();

        float sum_a = 0.f, sum_b = 0.f;
        {
            int r0 = (lane >> 2);
            int cc = 2 * (lane & 3);
#pragma unroll
            for (int nt = 0; nt < 8; nt++) {
                float p0 = __expf(sacc[nt][0] - mn_a);
                float p1 = __expf(sacc[nt][1] - mn_a);
                float p2 = __expf(sacc[nt][2] - mn_b);
                float p3 = __expf(sacc[nt][3] - mn_b);
                sum_a += p0 + p1;
                sum_b += p2 + p3;
                int col = nt * 8 + cc;
                *(__half2*)(Pw + r0 * PS + col) =
                    __float22half2_rn(make_float2(p0, p1));
                *(__half2*)(Pw + (r0 + 8) * PS + col) =
                    __float22half2_rn(make_float2(p2, p3));
            }
        }
        sum_a += __shfl_xor_sync(0xffffffffu, sum_a, 1);
        sum_a += __shfl_xor_sync(0xffffffffu, sum_a, 2);
        sum_b += __shfl_xor_sync(0xffffffffu, sum_b, 1);
        sum_b += __shfl_xor_sync(0xffffffffu, sum_b, 2);
        l_a = l_a * al_a + sum_a;
        l_b = l_b * al_b + sum_b;

#pragma unroll
        for (int nt = 0; nt < 12; nt++) {
            oacc[nt][0] *= al_a; oacc[nt][1] *= al_a;
            oacc[nt][2] *= al_b; oacc[nt][3] *= al_b;
        }

        __syncwarp();

        // ---- O += P V ----
#pragma unroll
        for (int jj = 0; jj < 4; jj++) {
            uint32_t af[4];
            ldsm4(af, sPw + (((idx & 1) * 8 + lrow) * PS
                             + jj * 16 + (idx >> 1) * 8) * 2);
#pragma unroll
            for (int dt2 = 0; dt2 < 6; dt2++) {
                uint32_t r[4];
                ldsm4t(r, sVb + ((jj * 16 + (idx & 1) * 8 + lrow) * VS
                                 + dt2 * 16 + (idx >> 1) * 8) * 2);
                uint32_t b0[2] = {r[0], r[1]};
                uint32_t b1[2] = {r[2], r[3]};
                mma_f16(oacc[2 * dt2], af, b0);
                mma_f16(oacc[2 * dt2 + 1], af, b1);
            }
        }
    }

    float invla = 1.0f / l_a;
    float invlb = 1.0f / l_b;
    int row0 = quarter * 64 + wid * 16 + (lane >> 2);
    __half* o0 = g_oh + (size_t)(bf * SEQ + row0) * DMODEL + h * HEADDIM;
    __half* o1 = g_oh + (size_t)(bf * SEQ + row0 + 8) * DMODEL + h * HEADDIM;
#pragma unroll
    for (int nt = 0; nt < 12; nt++) {
        int col = nt * 8 + 2 * (lane & 3);
        *(__half2*)(o0 + col) = __float22half2_rn(
            make_float2(oacc[nt][0] * invla, oacc[nt][1] * invla));
        *(__half2*)(o1 + col) = __float22half2_rn(
            make_float2(oacc[nt][2] * invlb, oacc[nt][3] * invlb));
    }
}

// ============================================================================
// launch
// ============================================================================
extern "C" void kernel_launch(void* const* d_in, const int* in_sizes, int n_in,
                              void* d_out, int out_size)
{
    const float* x     = (const float*)d_in[0];
    const float* w_qkv = (const float*)d_in[1];
    const float* w_o   = (const float*)d_in[2];
    float* out = (float*)d_out;

    __half *xh_p, *wh_p, *qkvh_p, *oh_p;
    cudaGetSymbolAddress((void**)&xh_p, g_xh);
    cudaGetSymbolAddress((void**)&wh_p, g_wh);
    cudaGetSymbolAddress((void**)&qkvh_p, g_qkvh);
    cudaGetSymbolAddress((void**)&oh_p, g_oh);

    cudaFuncSetAttribute(gemm_f16<__half>,
                         cudaFuncAttributeMaxDynamicSharedMemorySize, GEMM_SMEM);
    cudaFuncSetAttribute(gemm_f16<float>,
                         cudaFuncAttributeMaxDynamicSharedMemorySize, GEMM_SMEM);
    cudaFuncSetAttribute(attn_kernel,
                         cudaFuncAttributeMaxDynamicSharedMemorySize, ATTN_SMEM);

    int n8;

    // convert x -> fp16, w_qkv -> fp16
    n8 = MTOK * DMODEL / 8;
    f32_to_f16_kernel<<<(n8 + 255) / 256, 256>>>((const float4*)x, (uint4*)xh_p, n8);
    n8 = QKV_N * DMODEL / 8;
    f32_to_f16_kernel<<<(n8 + 255) / 256, 256>>>((const float4*)w_qkv, (uint4*)wh_p, n8);

    // 1) QKV projection: qkvh[32768,1920] = xh @ w_qkv^T  (fp16 out, 2 CTAs/SM)
    gemm_f16<__half><<<dim3(QKV_N / 128, MTOK / 128), 128, GEMM_SMEM>>>(
        xh_p, wh_p, qkvh_p, QKV_N, DMODEL);

    // 2) qk-norm + spatial RoPE + transpose (fp16 q/k/v)
    {
        int total_warps = MTOK * NHEADS + 2 * MTOK * NGROUPS;
        normrope_kernel<<<total_warps / 8, 256>>>(qkvh_p);
    }

    // 3) flash attention (fp16 mma, 2 CTAs/SM, double-buffered K/V)
    attn_kernel<<<dim3(4, NHEADS, BFRAMES), 128, ATTN_SMEM>>>();

    // convert w_o -> fp16
    n8 = DMODEL * DMODEL / 8;
    f32_to_f16_kernel<<<(n8 + 255) / 256, 256>>>((const float4*)w_o, (uint4*)wh_p, n8);

    // 4) output projection: out[32768,1152] = oh @ w_o^T  (fp32 out, 2 CTAs/SM)
    gemm_f16<float><<<dim3(DMODEL / 128, MTOK / 128), 128, GEMM_SMEM>>>(
        oh_p, wh_p, out, DMODEL, DMODEL);
}

// round 13
// speedup vs baseline: 1.2456x; 1.0353x over previous
#include <cuda_runtime.h>
#include <cuda_fp16.h>
#include <math.h>
#include <stdint.h>

// ---------------- problem constants (fixed by setup_inputs) ----------------
#define BFRAMES   128          // B*T = 8*16
#define SEQ       256          // H*W = 16*16
#define DMODEL    1152
#define NHEADS    12
#define NGROUPS   4
#define HEADDIM   96
#define QKV_N     1920         // 12*96 + 2*4*96
#define MTOK      32768        // BFRAMES*SEQ
#define SM_SCALE  0.1020620726159658f   // 96^-0.5

// ---------------- scratch (device globals; no allocation allowed) ----------
__device__ __half g_xh[(size_t)MTOK * DMODEL];      // fp16 x
__device__ __half g_wh[(size_t)QKV_N * DMODEL];     // fp16 weights (reused)
__device__ __half g_qkvh[(size_t)MTOK * QKV_N];     // fp16 qkv
__device__ __half g_qh[(size_t)BFRAMES * NHEADS * SEQ * HEADDIM];
__device__ __half g_kh[(size_t)BFRAMES * NGROUPS * SEQ * HEADDIM];
__device__ __half g_vh[(size_t)BFRAMES * NGROUPS * SEQ * HEADDIM];
__device__ __half g_oh[(size_t)MTOK * DMODEL];      // fp16 attention output

// ============================================================================
// helpers
// ============================================================================
__device__ __forceinline__ uint32_t smem_u32(const void* p) {
    uint32_t a;
    asm("{ .reg .u64 t; cvta.to.shared.u64 t, %1; cvt.u32.u64 %0, t; }"
        : "=r"(a) : "l"(p));
    return a;
}

__device__ __forceinline__ void cp_async16(uint32_t saddr, const void* gptr) {
    asm volatile("cp.async.cg.shared.global [%0], [%1], 16;" :: "r"(saddr), "l"(gptr));
}

__device__ __forceinline__ void mma_f16(float c[4], const uint32_t a[4],
                                        const uint32_t b[2]) {
    asm volatile(
        "mma.sync.aligned.m16n8k16.row.col.f32.f16.f16.f32 "
        "{%0,%1,%2,%3}, {%4,%5,%6,%7}, {%8,%9}, {%0,%1,%2,%3};"
        : "+f"(c[0]), "+f"(c[1]), "+f"(c[2]), "+f"(c[3])
        : "r"(a[0]), "r"(a[1]), "r"(a[2]), "r"(a[3]), "r"(b[0]), "r"(b[1]));
}

__device__ __forceinline__ void ldsm4(uint32_t r[4], uint32_t addr) {
    asm volatile("ldmatrix.sync.aligned.m8n8.x4.shared.b16 {%0,%1,%2,%3}, [%4];"
                 : "=r"(r[0]), "=r"(r[1]), "=r"(r[2]), "=r"(r[3]) : "r"(addr));
}

__device__ __forceinline__ void ldsm4t(uint32_t r[4], uint32_t addr) {
    asm volatile("ldmatrix.sync.aligned.m8n8.x4.trans.shared.b16 {%0,%1,%2,%3}, [%4];"
                 : "=r"(r[0]), "=r"(r[1]), "=r"(r[2]), "=r"(r[3]) : "r"(addr));
}

// ============================================================================
// fp16 mma.sync GEMM (NT): C[M,N] = A[M,K] * B[N,K]^T, fp32 accumulate.
// 128-thread CTAs, 128x128 tile, 2 CTAs/SM. BK=64, 3-stage cp.async,
// single __syncthreads per iter, warp tile 64x64, reg double-buffered frags.
// (R12-proven)
// ============================================================================
#define HSTR      72
#define STAGE_H   ((128 + 128) * HSTR)       // 18432 halves
#define GEMM_SMEM (3 * STAGE_H * 2)          // 110592 bytes (x2 CTAs = 221KB < 227KB)

template <typename OT>
__global__ __launch_bounds__(128, 2)
void gemm_f16(const __half* __restrict__ A, const __half* __restrict__ B,
              OT* __restrict__ C, int ldC, int K)
{
    extern __shared__ __half smh[];
    const int tid    = threadIdx.x;
    const int lane   = tid & 31;
    const int wid    = tid >> 5;         // 0..3
    const int warp_m = wid & 1;
    const int warp_n = wid >> 1;
    const int m0 = blockIdx.y * 128;
    const int n0 = blockIdx.x * 128;
    const int ITERS = K >> 6;            // BK = 64

    const __half* Ag = A + (size_t)m0 * K;
    const __half* Bg = B + (size_t)n0 * K;
    const uint32_t sbase = smem_u32(smh);

    auto load_stage = [&](int chunk, int st) {
        uint32_t abase = sbase + st * (STAGE_H * 2);
        uint32_t bbase = abase + 128 * (HSTR * 2);
        const __half* Ac = Ag + chunk * 64;
        const __half* Bc = Bg + chunk * 64;
#pragma unroll
        for (int j = 0; j < 8; j++) {
            int idx = tid + j * 128;
            int row = idx >> 3, c = idx & 7;
            cp_async16(abase + row * (HSTR * 2) + c * 16,
                       Ac + (size_t)row * K + c * 8);
        }
#pragma unroll
        for (int j = 0; j < 8; j++) {
            int idx = tid + j * 128;
            int row = idx >> 3, c = idx & 7;
            cp_async16(bbase + row * (HSTR * 2) + c * 16,
                       Bc + (size_t)row * K + c * 8);
        }
    };

    float acc[4][8][4];
#pragma unroll
    for (int mt = 0; mt < 4; mt++)
#pragma unroll
        for (int nt = 0; nt < 8; nt++)
#pragma unroll
            for (int r = 0; r < 4; r++) acc[mt][nt][r] = 0.f;

    const int arow = warp_m * 64 + (lane & 15);
    const int acol = (lane >> 4) * 8;
    const int brow = warp_n * 64 + (lane & 7) + (lane >> 4) * 8;
    const int bcol = ((lane >> 3) & 1) * 8;

    load_stage(0, 0);
    asm volatile("cp.async.commit_group;");
    if (ITERS > 1) load_stage(1, 1);
    asm volatile("cp.async.commit_group;");

    for (int i = 0; i < ITERS; i++) {
        asm volatile("cp.async.wait_group 1;");
        __syncthreads();

        if (i + 2 < ITERS) load_stage(i + 2, (i + 2) % 3);
        asm volatile("cp.async.commit_group;");

        const int st = i % 3;
        uint32_t abase = sbase + st * (STAGE_H * 2);
        uint32_t bbase = abase + 128 * (HSTR * 2);

        auto load_frags = [&](int kstep, uint32_t af[4][4], uint32_t bf[8][2]) {
#pragma unroll
            for (int mt = 0; mt < 4; mt++)
                ldsm4(af[mt], abase + ((arow + mt * 16) * HSTR
                                       + kstep * 16 + acol) * 2);
#pragma unroll
            for (int ntp = 0; ntp < 4; ntp++) {
                uint32_t r[4];
                ldsm4(r, bbase + ((brow + ntp * 16) * HSTR
                                  + kstep * 16 + bcol) * 2);
                bf[2 * ntp][0] = r[0]; bf[2 * ntp][1] = r[1];
                bf[2 * ntp + 1][0] = r[2]; bf[2 * ntp + 1][1] = r[3];
            }
        };

        uint32_t af[2][4][4];
        uint32_t bf[2][8][2];
        load_frags(0, af[0], bf[0]);

#pragma unroll
        for (int kstep = 0; kstep < 4; kstep++) {
            const int cur = kstep & 1;
            const int nxt = cur ^ 1;
            if (kstep < 3) load_frags(kstep + 1, af[nxt], bf[nxt]);
#pragma unroll
            for (int mt = 0; mt < 4; mt++)
#pragma unroll
                for (int nt = 0; nt < 8; nt++)
                    mma_f16(acc[mt][nt], af[cur][mt], bf[cur][nt]);
        }
    }

#pragma unroll
    for (int mt = 0; mt < 4; mt++) {
        int row0 = m0 + warp_m * 64 + mt * 16 + (lane >> 2);
#pragma unroll
        for (int nt = 0; nt < 8; nt++) {
            int col = n0 + warp_n * 64 + nt * 8 + (lane & 3) * 2;
            if constexpr (sizeof(OT) == 4) {
                *(float2*)((float*)C + (size_t)row0 * ldC + col) =
                    make_float2(acc[mt][nt][0], acc[mt][nt][1]);
                *(float2*)((float*)C + (size_t)(row0 + 8) * ldC + col) =
                    make_float2(acc[mt][nt][2], acc[mt][nt][3]);
            } else {
                *(__half2*)((__half*)C + (size_t)row0 * ldC + col) =
                    __float22half2_rn(make_float2(acc[mt][nt][0], acc[mt][nt][1]));
                *(__half2*)((__half*)C + (size_t)(row0 + 8) * ldC + col) =
                    __float22half2_rn(make_float2(acc[mt][nt][2], acc[mt][nt][3]));
            }
        }
    }
}

// ============================================================================
// convert fp32 -> fp16 (RN), 8 elems per thread
// ============================================================================
__global__ __launch_bounds__(256) void f32_to_f16_kernel(
    const float4* __restrict__ in, uint4* __restrict__ out, int n8)
{
    int i = blockIdx.x * blockDim.x + threadIdx.x;
    if (i >= n8) return;
    float4 a = in[2 * i], b = in[2 * i + 1];
    __half2 h0 = __float22half2_rn(make_float2(a.x, a.y));
    __half2 h1 = __float22half2_rn(make_float2(a.z, a.w));
    __half2 h2 = __float22half2_rn(make_float2(b.x, b.y));
    __half2 h3 = __float22half2_rn(make_float2(b.z, b.w));
    uint4 o;
    o.x = *(uint32_t*)&h0; o.y = *(uint32_t*)&h1;
    o.z = *(uint32_t*)&h2; o.w = *(uint32_t*)&h3;
    out[i] = o;
}

// ============================================================================
// norm + RoPE + layout transpose v2: ONE HALF-WARP (16 lanes) PER VECTOR.
// Lane l16 holds half2 slots {l16, l16+16, l16+32}; slot s = dims (2s, 2s+1).
// Norm: 4-shuffle reduction over 16 lanes. RoPE: output slot l16 needs input
// slots 2*(l16&7) and 2*(l16&7)+1 -> 4 fp32 shuffles + 2 __sincosf per lane.
// Vector pairs per warp are always adjacent in qkv memory (NHEADS, NGROUPS,
// NQv, NKv all even), so loads coalesce.
// ============================================================================
__global__ __launch_bounds__(256) void normrope_kernel(const __half* __restrict__ qkv)
{
    const int NQv = MTOK * NHEADS;
    const int NKv = MTOK * NGROUPS;
    int gw   = (blockIdx.x * blockDim.x + threadIdx.x) >> 5;
    int lane = threadIdx.x & 31;
    int l16  = lane & 15;
    int vu   = gw * 2 + (lane >> 4);          // vector unit id
    if (vu >= NQv + 2 * NKv) return;

    const __half* src;
    __half* dst;
    int t;
    bool do_nr = true;

    if (vu < NQv) {
        t = vu / NHEADS; int h = vu % NHEADS;
        src = qkv + (size_t)t * QKV_N + h * HEADDIM;
        int bf = t >> 8, s = t & 255;
        dst = g_qh + ((size_t)(bf * NHEADS + h) * SEQ + s) * HEADDIM;
    } else if (vu < NQv + NKv) {
        int v = vu - NQv; t = v / NGROUPS; int g = v % NGROUPS;
        src = qkv + (size_t)t * QKV_N + DMODEL + g * HEADDIM;
        int bf = t >> 8, s = t & 255;
        dst = g_kh + ((size_t)(bf * NGROUPS + g) * SEQ + s) * HEADDIM;
    } else {
        int v = vu - NQv - NKv; t = v / NGROUPS; int g = v % NGROUPS;
        src = qkv + (size_t)t * QKV_N + DMODEL + NGROUPS * HEADDIM + g * HEADDIM;
        int bf = t >> 8, s = t & 255;
        dst = g_vh + ((size_t)(bf * NGROUPS + g) * SEQ + s) * HEADDIM;
        do_nr = false;
    }

    const __half2* sp = (const __half2*)src;
    __half2* dp = (__half2*)dst;
    float2 f0 = __half22float2(sp[l16]);
    float2 f1 = __half22float2(sp[l16 + 16]);
    float2 f2 = __half22float2(sp[l16 + 32]);

    if (do_nr) {
        float ss = f0.x * f0.x + f0.y * f0.y
                 + f1.x * f1.x + f1.y * f1.y
                 + f2.x * f2.x + f2.y * f2.y;
#pragma unroll
        for (int o = 8; o; o >>= 1) ss += __shfl_xor_sync(0xffffffffu, ss, o);
        float inv = 1.0f / fmaxf(sqrtf(ss), 1e-10f);
        f0.x *= inv; f0.y *= inv;
        f1.x *= inv; f1.y *= inv;
        f2.x *= inv; f2.y *= inv;

        // spatial RoPE on dims 0..31 (slots 0..15 == reg f0)
        int s = t & 255;
        float pos = (float)((s >> 4) + (s & 15));
        int lh = l16 & 7;
        int sA = (lane & 16) + 2 * lh;        // source lane (same half-warp)
        float xA0 = __shfl_sync(0xffffffffu, f0.x, sA);
        float xA1 = __shfl_sync(0xffffffffu, f0.y, sA);
        float xB0 = __shfl_sync(0xffffffffu, f0.x, sA + 1);
        float xB1 = __shfl_sync(0xffffffffu, f0.y, sA + 1);
        float angA = pos * exp2f(-(float)(2 * lh) * 0.8304820237218406f);
        float angB = pos * exp2f(-(float)(2 * lh + 1) * 0.8304820237218406f);
        float sa, ca, sb, cb;
        __sincosf(angA, &sa, &ca);
        __sincosf(angB, &sb, &cb);
        if (l16 < 8) {          // out dims [0,16): x1*cos - x2*sin
            f0.x = fmaf(xA0, ca, -xA1 * sa);
            f0.y = fmaf(xB0, cb, -xB1 * sb);
        } else {                // out dims [16,32): x1*sin + x2*cos
            f0.x = fmaf(xA0, sa, xA1 * ca);
            f0.y = fmaf(xB0, sb, xB1 * cb);
        }
    }

    dp[l16]      = __float22half2_rn(f0);
    dp[l16 + 16] = __float22half2_rn(f1);
    dp[l16 + 32] = __float22half2_rn(f2);
}

// ============================================================================
// Flash attention, fp16 mma.sync m16n8k16, fp32 accum/softmax. (R10-proven)
// 128-thread CTAs (4 warps, 64 q-rows), 2 CTAs/SM, double-buffered K/V.
// ============================================================================
#define KS 104
#define VS 104
#define PS 72
#define KV_STG   (64 * (KS + VS))                       // halves per stage
#define ATTN_SMEM ((2 * KV_STG + 64 * PS) * 2)          // 62464 bytes

__global__ __launch_bounds__(128, 2) void attn_kernel()
{
    extern __shared__ __half smh[];
    const uint32_t sbase = smem_u32(smh);

    const int tid  = threadIdx.x;
    const int lane = tid & 31;
    const int wid  = tid >> 5;          // 0..3
    const int quarter = blockIdx.x;     // 0..3 (64 q-rows each)
    const int h    = blockIdx.y;
    const int bf   = blockIdx.z;
    const int g    = h / 3;

    const __half* Qg = g_qh + ((size_t)(bf * NHEADS + h) * SEQ
                               + quarter * 64 + wid * 16) * HEADDIM;
    const __half* Kg = g_kh + (size_t)(bf * NGROUPS + g) * SEQ * HEADDIM;
    const __half* Vg = g_vh + (size_t)(bf * NGROUPS + g) * SEQ * HEADDIM;

    uint32_t qf[6][4];
    {
        const __half* q0 = Qg + (lane >> 2) * HEADDIM;
        const __half* q1 = Qg + ((lane >> 2) + 8) * HEADDIM;
        int cc = 2 * (lane & 3);
#pragma unroll
        for (int j = 0; j < 6; j++) {
            qf[j][0] = *(const uint32_t*)(q0 + j * 16 + cc);
            qf[j][1] = *(const uint32_t*)(q1 + j * 16 + cc);
            qf[j][2] = *(const uint32_t*)(q0 + j * 16 + 8 + cc);
            qf[j][3] = *(const uint32_t*)(q1 + j * 16 + 8 + cc);
        }
    }

    const uint32_t sPw = sbase + (2 * KV_STG + wid * 16 * PS) * 2;
    __half* Pw = smh + 2 * KV_STG + wid * 16 * PS;

    const int idx  = lane >> 3;
    const int lrow = lane & 7;

    auto load_kv = [&](int kt, int st) {
        uint32_t kb = sbase + st * (KV_STG * 2);
        uint32_t vb = kb + 64 * KS * 2;
        const __half* Kc = Kg + (size_t)kt * 64 * HEADDIM;
        const __half* Vc = Vg + (size_t)kt * 64 * HEADDIM;
#pragma unroll
        for (int it = 0; it < 6; it++) {
            int i = tid + it * 128;
            int r = i / 12, c = (i % 12) * 8;
            cp_async16(kb + (r * KS + c) * 2, Kc + r * HEADDIM + c);
            cp_async16(vb + (r * VS + c) * 2, Vc + r * HEADDIM + c);
        }
    };

    float m_a = -INFINITY, m_b = -INFINITY;
    float l_a = 0.f, l_b = 0.f;
    float oacc[12][4];
#pragma unroll
    for (int nt = 0; nt < 12; nt++)
#pragma unroll
        for (int r = 0; r < 4; r++) oacc[nt][r] = 0.f;

    load_kv(0, 0);
    asm volatile("cp.async.commit_group;");

    for (int kt = 0; kt < 4; kt++) {
        __syncthreads();
        if (kt < 3) {
            load_kv(kt + 1, (kt + 1) & 1);
            asm volatile("cp.async.commit_group;");
            asm volatile("cp.async.wait_group 1;");
        } else {
            asm volatile("cp.async.wait_group 0;");
        }
        __syncthreads();

        const int st = kt & 1;
        const uint32_t sKb = sbase + st * (KV_STG * 2);
        const uint32_t sVb = sKb + 64 * KS * 2;

        // ---- S = Q K^T ----
        float sacc[8][4];
#pragma unroll
        for (int nt = 0; nt < 8; nt++)
#pragma unroll
            for (int r = 0; r < 4; r++) sacc[nt][r] = 0.f;

#pragma unroll
        for (int j = 0; j < 6; j++) {
#pragma unroll
            for (int nt2 = 0; nt2 < 4; nt2++) {
                uint32_t r[4];
                ldsm4(r, sKb + ((nt2 * 16 + (idx >> 1) * 8 + lrow) * KS
                                + j * 16 + (idx & 1) * 8) * 2);
                uint32_t b0[2] = {r[0], r[1]};
                uint32_t b1[2] = {r[2], r[3]};
                mma_f16(sacc[2 * nt2], qf[j], b0);
                mma_f16(sacc[2 * nt2 + 1], qf[j], b1);
            }
        }

        // ---- online softmax ----
        float tmax_a = -INFINITY, tmax_b = -INFINITY;
#pragma unroll
        for (int nt = 0; nt < 8; nt++) {
#pragma unroll
            for (int r = 0; r < 4; r++) sacc[nt][r] *= SM_SCALE;
            tmax_a = fmaxf(tmax_a, fmaxf(sacc[nt][0], sacc[nt][1]));
            tmax_b = fmaxf(tmax_b, fmaxf(sacc[nt][2], sacc[nt][3]));
        }
        tmax_a = fmaxf(tmax_a, __shfl_xor_sync(0xffffffffu, tmax_a, 1));
        tmax_a = fmaxf(tmax_a, __shfl_xor_sync(0xffffffffu, tmax_a, 2));
        tmax_b = fmaxf(tmax_b, __shfl_xor_sync(0xffffffffu, tmax_b, 1));
        tmax_b = fmaxf(tmax_b, __shfl_xor_sync(0xffffffffu, tmax_b, 2));

        float mn_a = fmaxf(m_a, tmax_a);
        float mn_b = fmaxf(m_b, tmax_b);
        float al_a = __expf(m_a - mn_a);
        float al_b = __expf(m_b - mn_b);
        m_a = mn_a; m_b = mn_b;

        __syncwarp();

        float sum_a = 0.f, sum_b = 0.f;
        {
            int r0 = (lane >> 2);
            int cc = 2 * (lane & 3);
#pragma unroll
            for (int nt = 0; nt < 8; nt++) {
                float p0 = __expf(sacc[nt][0] - mn_a);
                float p1 = __expf(sacc[nt][1] - mn_a);
                float p2 = __expf(sacc[nt][2] - mn_b);
                float p3 = __expf(sacc[nt][3] - mn_b);
                sum_a += p0 + p1;
                sum_b += p2 + p3;
                int col = nt * 8 + cc;
                *(__half2*)(Pw + r0 * PS + col) =
                    __float22half2_rn(make_float2(p0, p1));
                *(__half2*)(Pw + (r0 + 8) * PS + col) =
                    __float22half2_rn(make_float2(p2, p3));
            }
        }
        sum_a += __shfl_xor_sync(0xffffffffu, sum_a, 1);
        sum_a += __shfl_xor_sync(0xffffffffu, sum_a, 2);
        sum_b += __shfl_xor_sync(0xffffffffu, sum_b, 1);
        sum_b += __shfl_xor_sync(0xffffffffu, sum_b, 2);
        l_a = l_a * al_a + sum_a;
        l_b = l_b * al_b + sum_b;

#pragma unroll
        for (int nt = 0; nt < 12; nt++) {
            oacc[nt][0] *= al_a; oacc[nt][1] *= al_a;
            oacc[nt][2] *= al_b; oacc[nt][3] *= al_b;
        }

        __syncwarp();

        // ---- O += P V ----
#pragma unroll
        for (int jj = 0; jj < 4; jj++) {
            uint32_t af[4];
            ldsm4(af, sPw + (((idx & 1) * 8 + lrow) * PS
                             + jj * 16 + (idx >> 1) * 8) * 2);
#pragma unroll
            for (int dt2 = 0; dt2 < 6; dt2++) {
                uint32_t r[4];
                ldsm4t(r, sVb + ((jj * 16 + (idx & 1) * 8 + lrow) * VS
                                 + dt2 * 16 + (idx >> 1) * 8) * 2);
                uint32_t b0[2] = {r[0], r[1]};
                uint32_t b1[2] = {r[2], r[3]};
                mma_f16(oacc[2 * dt2], af, b0);
                mma_f16(oacc[2 * dt2 + 1], af, b1);
            }
        }
    }

    float invla = 1.0f / l_a;
    float invlb = 1.0f / l_b;
    int row0 = quarter * 64 + wid * 16 + (lane >> 2);
    __half* o0 = g_oh + (size_t)(bf * SEQ + row0) * DMODEL + h * HEADDIM;
    __half* o1 = g_oh + (size_t)(bf * SEQ + row0 + 8) * DMODEL + h * HEADDIM;
#pragma unroll
    for (int nt = 0; nt < 12; nt++) {
        int col = nt * 8 + 2 * (lane & 3);
        *(__half2*)(o0 + col) = __float22half2_rn(
            make_float2(oacc[nt][0] * invla, oacc[nt][1] * invla));
        *(__half2*)(o1 + col) = __float22half2_rn(
            make_float2(oacc[nt][2] * invlb, oacc[nt][3] * invlb));
    }
}

// ============================================================================
// launch
// ============================================================================
extern "C" void kernel_launch(void* const* d_in, const int* in_sizes, int n_in,
                              void* d_out, int out_size)
{
    const float* x     = (const float*)d_in[0];
    const float* w_qkv = (const float*)d_in[1];
    const float* w_o   = (const float*)d_in[2];
    float* out = (float*)d_out;

    __half *xh_p, *wh_p, *qkvh_p, *oh_p;
    cudaGetSymbolAddress((void**)&xh_p, g_xh);
    cudaGetSymbolAddress((void**)&wh_p, g_wh);
    cudaGetSymbolAddress((void**)&qkvh_p, g_qkvh);
    cudaGetSymbolAddress((void**)&oh_p, g_oh);

    cudaFuncSetAttribute(gemm_f16<__half>,
                         cudaFuncAttributeMaxDynamicSharedMemorySize, GEMM_SMEM);
    cudaFuncSetAttribute(gemm_f16<float>,
                         cudaFuncAttributeMaxDynamicSharedMemorySize, GEMM_SMEM);
    cudaFuncSetAttribute(attn_kernel,
                         cudaFuncAttributeMaxDynamicSharedMemorySize, ATTN_SMEM);

    int n8;

    // convert x -> fp16, w_qkv -> fp16
    n8 = MTOK * DMODEL / 8;
    f32_to_f16_kernel<<<(n8 + 255) / 256, 256>>>((const float4*)x, (uint4*)xh_p, n8);
    n8 = QKV_N * DMODEL / 8;
    f32_to_f16_kernel<<<(n8 + 255) / 256, 256>>>((const float4*)w_qkv, (uint4*)wh_p, n8);

    // 1) QKV projection: qkvh[32768,1920] = xh @ w_qkv^T  (fp16 out, 2 CTAs/SM)
    gemm_f16<__half><<<dim3(QKV_N / 128, MTOK / 128), 128, GEMM_SMEM>>>(
        xh_p, wh_p, qkvh_p, QKV_N, DMODEL);

    // 2) qk-norm + spatial RoPE + transpose (half-warp per vector)
    {
        int total_vec = MTOK * NHEADS + 2 * MTOK * NGROUPS;  // 655360
        int warps = total_vec / 2;                            // 327680
        normrope_kernel<<<warps / 8, 256>>>(qkvh_p);
    }

    // 3) flash attention (fp16 mma, 2 CTAs/SM, double-buffered K/V)
    attn_kernel<<<dim3(4, NHEADS, BFRAMES), 128, ATTN_SMEM>>>();

    // convert w_o -> fp16
    n8 = DMODEL * DMODEL / 8;
    f32_to_f16_kernel<<<(n8 + 255) / 256, 256>>>((const float4*)w_o, (uint4*)wh_p, n8);

    // 4) output projection: out[32768,1152] = oh @ w_o^T  (fp32 out, 2 CTAs/SM)
    gemm_f16<float><<<dim3(DMODEL / 128, MTOK / 128), 128, GEMM_SMEM>>>(
        oh_p, wh_p, out, DMODEL, DMODEL);
}

// round 14
// speedup vs baseline: 1.2666x; 1.0168x over previous
#include <cuda_runtime.h>
#include <cuda_fp16.h>
#include <math.h>
#include <stdint.h>

// ---------------- problem constants (fixed by setup_inputs) ----------------
#define BFRAMES   128          // B*T = 8*16
#define SEQ       256          // H*W = 16*16
#define DMODEL    1152
#define NHEADS    12
#define NGROUPS   4
#define HEADDIM   96
#define QKV_N     1920         // 12*96 + 2*4*96
#define MTOK      32768        // BFRAMES*SEQ
#define SM_SCALE  0.1020620726159658f   // 96^-0.5

// ---------------- scratch (device globals; no allocation allowed) ----------
__device__ __half g_xh[(size_t)MTOK * DMODEL];      // fp16 x
__device__ __half g_wh[(size_t)QKV_N * DMODEL];     // fp16 weights (reused)
__device__ __half g_qkvh[(size_t)MTOK * QKV_N];     // fp16 qkv
__device__ __half g_qh[(size_t)BFRAMES * NHEADS * SEQ * HEADDIM];
__device__ __half g_kh[(size_t)BFRAMES * NGROUPS * SEQ * HEADDIM];
__device__ __half g_vh[(size_t)BFRAMES * NGROUPS * SEQ * HEADDIM];
__device__ __half g_oh[(size_t)MTOK * DMODEL];      // fp16 attention output

// ============================================================================
// helpers
// ============================================================================
__device__ __forceinline__ uint32_t smem_u32(const void* p) {
    uint32_t a;
    asm("{ .reg .u64 t; cvta.to.shared.u64 t, %1; cvt.u32.u64 %0, t; }"
        : "=r"(a) : "l"(p));
    return a;
}

__device__ __forceinline__ void cp_async16(uint32_t saddr, const void* gptr) {
    asm volatile("cp.async.cg.shared.global [%0], [%1], 16;" :: "r"(saddr), "l"(gptr));
}

__device__ __forceinline__ void mma_f16(float c[4], const uint32_t a[4],
                                        const uint32_t b[2]) {
    asm volatile(
        "mma.sync.aligned.m16n8k16.row.col.f32.f16.f16.f32 "
        "{%0,%1,%2,%3}, {%4,%5,%6,%7}, {%8,%9}, {%0,%1,%2,%3};"
        : "+f"(c[0]), "+f"(c[1]), "+f"(c[2]), "+f"(c[3])
        : "r"(a[0]), "r"(a[1]), "r"(a[2]), "r"(a[3]), "r"(b[0]), "r"(b[1]));
}

__device__ __forceinline__ void ldsm4(uint32_t r[4], uint32_t addr) {
    asm volatile("ldmatrix.sync.aligned.m8n8.x4.shared.b16 {%0,%1,%2,%3}, [%4];"
                 : "=r"(r[0]), "=r"(r[1]), "=r"(r[2]), "=r"(r[3]) : "r"(addr));
}

__device__ __forceinline__ void ldsm4t(uint32_t r[4], uint32_t addr) {
    asm volatile("ldmatrix.sync.aligned.m8n8.x4.trans.shared.b16 {%0,%1,%2,%3}, [%4];"
                 : "=r"(r[0]), "=r"(r[1]), "=r"(r[2]), "=r"(r[3]) : "r"(addr));
}

__device__ __forceinline__ uint32_t pack_h2(float a, float b) {
    __half2 h = __float22half2_rn(make_float2(a, b));
    return *(uint32_t*)&h;
}

// ============================================================================
// fp16 mma.sync GEMM (NT): C[M,N] = A[M,K] * B[N,K]^T, fp32 accumulate.
// 128-thread CTAs, 128x128 tile, 2 CTAs/SM. BK=64, 3-stage cp.async,
// single __syncthreads per iter, warp tile 64x64, reg double-buffered frags.
// (R12-proven)
// ============================================================================
#define HSTR      72
#define STAGE_H   ((128 + 128) * HSTR)       // 18432 halves
#define GEMM_SMEM (3 * STAGE_H * 2)          // 110592 bytes (x2 CTAs = 221KB < 227KB)

template <typename OT>
__global__ __launch_bounds__(128, 2)
void gemm_f16(const __half* __restrict__ A, const __half* __restrict__ B,
              OT* __restrict__ C, int ldC, int K)
{
    extern __shared__ __half smh[];
    const int tid    = threadIdx.x;
    const int lane   = tid & 31;
    const int wid    = tid >> 5;         // 0..3
    const int warp_m = wid & 1;
    const int warp_n = wid >> 1;
    const int m0 = blockIdx.y * 128;
    const int n0 = blockIdx.x * 128;
    const int ITERS = K >> 6;            // BK = 64

    const __half* Ag = A + (size_t)m0 * K;
    const __half* Bg = B + (size_t)n0 * K;
    const uint32_t sbase = smem_u32(smh);

    auto load_stage = [&](int chunk, int st) {
        uint32_t abase = sbase + st * (STAGE_H * 2);
        uint32_t bbase = abase + 128 * (HSTR * 2);
        const __half* Ac = Ag + chunk * 64;
        const __half* Bc = Bg + chunk * 64;
#pragma unroll
        for (int j = 0; j < 8; j++) {
            int idx = tid + j * 128;
            int row = idx >> 3, c = idx & 7;
            cp_async16(abase + row * (HSTR * 2) + c * 16,
                       Ac + (size_t)row * K + c * 8);
        }
#pragma unroll
        for (int j = 0; j < 8; j++) {
            int idx = tid + j * 128;
            int row = idx >> 3, c = idx & 7;
            cp_async16(bbase + row * (HSTR * 2) + c * 16,
                       Bc + (size_t)row * K + c * 8);
        }
    };

    float acc[4][8][4];
#pragma unroll
    for (int mt = 0; mt < 4; mt++)
#pragma unroll
        for (int nt = 0; nt < 8; nt++)
#pragma unroll
            for (int r = 0; r < 4; r++) acc[mt][nt][r] = 0.f;

    const int arow = warp_m * 64 + (lane & 15);
    const int acol = (lane >> 4) * 8;
    const int brow = warp_n * 64 + (lane & 7) + (lane >> 4) * 8;
    const int bcol = ((lane >> 3) & 1) * 8;

    load_stage(0, 0);
    asm volatile("cp.async.commit_group;");
    if (ITERS > 1) load_stage(1, 1);
    asm volatile("cp.async.commit_group;");

    for (int i = 0; i < ITERS; i++) {
        asm volatile("cp.async.wait_group 1;");
        __syncthreads();

        if (i + 2 < ITERS) load_stage(i + 2, (i + 2) % 3);
        asm volatile("cp.async.commit_group;");

        const int st = i % 3;
        uint32_t abase = sbase + st * (STAGE_H * 2);
        uint32_t bbase = abase + 128 * (HSTR * 2);

        auto load_frags = [&](int kstep, uint32_t af[4][4], uint32_t bf[8][2]) {
#pragma unroll
            for (int mt = 0; mt < 4; mt++)
                ldsm4(af[mt], abase + ((arow + mt * 16) * HSTR
                                       + kstep * 16 + acol) * 2);
#pragma unroll
            for (int ntp = 0; ntp < 4; ntp++) {
                uint32_t r[4];
                ldsm4(r, bbase + ((brow + ntp * 16) * HSTR
                                  + kstep * 16 + bcol) * 2);
                bf[2 * ntp][0] = r[0]; bf[2 * ntp][1] = r[1];
                bf[2 * ntp + 1][0] = r[2]; bf[2 * ntp + 1][1] = r[3];
            }
        };

        uint32_t af[2][4][4];
        uint32_t bf[2][8][2];
        load_frags(0, af[0], bf[0]);

#pragma unroll
        for (int kstep = 0; kstep < 4; kstep++) {
            const int cur = kstep & 1;
            const int nxt = cur ^ 1;
            if (kstep < 3) load_frags(kstep + 1, af[nxt], bf[nxt]);
#pragma unroll
            for (int mt = 0; mt < 4; mt++)
#pragma unroll
                for (int nt = 0; nt < 8; nt++)
                    mma_f16(acc[mt][nt], af[cur][mt], bf[cur][nt]);
        }
    }

#pragma unroll
    for (int mt = 0; mt < 4; mt++) {
        int row0 = m0 + warp_m * 64 + mt * 16 + (lane >> 2);
#pragma unroll
        for (int nt = 0; nt < 8; nt++) {
            int col = n0 + warp_n * 64 + nt * 8 + (lane & 3) * 2;
            if constexpr (sizeof(OT) == 4) {
                *(float2*)((float*)C + (size_t)row0 * ldC + col) =
                    make_float2(acc[mt][nt][0], acc[mt][nt][1]);
                *(float2*)((float*)C + (size_t)(row0 + 8) * ldC + col) =
                    make_float2(acc[mt][nt][2], acc[mt][nt][3]);
            } else {
                *(__half2*)((__half*)C + (size_t)row0 * ldC + col) =
                    __float22half2_rn(make_float2(acc[mt][nt][0], acc[mt][nt][1]));
                *(__half2*)((__half*)C + (size_t)(row0 + 8) * ldC + col) =
                    __float22half2_rn(make_float2(acc[mt][nt][2], acc[mt][nt][3]));
            }
        }
    }
}

// ============================================================================
// convert fp32 -> fp16 (RN), 8 elems per thread
// ============================================================================
__global__ __launch_bounds__(256) void f32_to_f16_kernel(
    const float4* __restrict__ in, uint4* __restrict__ out, int n8)
{
    int i = blockIdx.x * blockDim.x + threadIdx.x;
    if (i >= n8) return;
    float4 a = in[2 * i], b = in[2 * i + 1];
    __half2 h0 = __float22half2_rn(make_float2(a.x, a.y));
    __half2 h1 = __float22half2_rn(make_float2(a.z, a.w));
    __half2 h2 = __float22half2_rn(make_float2(b.x, b.y));
    __half2 h3 = __float22half2_rn(make_float2(b.z, b.w));
    uint4 o;
    o.x = *(uint32_t*)&h0; o.y = *(uint32_t*)&h1;
    o.z = *(uint32_t*)&h2; o.w = *(uint32_t*)&h3;
    out[i] = o;
}

// ============================================================================
// norm + RoPE + layout transpose: half-warp per vector (R13-proven)
// ============================================================================
__global__ __launch_bounds__(256) void normrope_kernel(const __half* __restrict__ qkv)
{
    const int NQv = MTOK * NHEADS;
    const int NKv = MTOK * NGROUPS;
    int gw   = (blockIdx.x * blockDim.x + threadIdx.x) >> 5;
    int lane = threadIdx.x & 31;
    int l16  = lane & 15;
    int vu   = gw * 2 + (lane >> 4);
    if (vu >= NQv + 2 * NKv) return;

    const __half* src;
    __half* dst;
    int t;
    bool do_nr = true;

    if (vu < NQv) {
        t = vu / NHEADS; int h = vu % NHEADS;
        src = qkv + (size_t)t * QKV_N + h * HEADDIM;
        int bf = t >> 8, s = t & 255;
        dst = g_qh + ((size_t)(bf * NHEADS + h) * SEQ + s) * HEADDIM;
    } else if (vu < NQv + NKv) {
        int v = vu - NQv; t = v / NGROUPS; int g = v % NGROUPS;
        src = qkv + (size_t)t * QKV_N + DMODEL + g * HEADDIM;
        int bf = t >> 8, s = t & 255;
        dst = g_kh + ((size_t)(bf * NGROUPS + g) * SEQ + s) * HEADDIM;
    } else {
        int v = vu - NQv - NKv; t = v / NGROUPS; int g = v % NGROUPS;
        src = qkv + (size_t)t * QKV_N + DMODEL + NGROUPS * HEADDIM + g * HEADDIM;
        int bf = t >> 8, s = t & 255;
        dst = g_vh + ((size_t)(bf * NGROUPS + g) * SEQ + s) * HEADDIM;
        do_nr = false;
    }

    const __half2* sp = (const __half2*)src;
    __half2* dp = (__half2*)dst;
    float2 f0 = __half22float2(sp[l16]);
    float2 f1 = __half22float2(sp[l16 + 16]);
    float2 f2 = __half22float2(sp[l16 + 32]);

    if (do_nr) {
        float ss = f0.x * f0.x + f0.y * f0.y
                 + f1.x * f1.x + f1.y * f1.y
                 + f2.x * f2.x + f2.y * f2.y;
#pragma unroll
        for (int o = 8; o; o >>= 1) ss += __shfl_xor_sync(0xffffffffu, ss, o);
        float inv = 1.0f / fmaxf(sqrtf(ss), 1e-10f);
        f0.x *= inv; f0.y *= inv;
        f1.x *= inv; f1.y *= inv;
        f2.x *= inv; f2.y *= inv;

        int s = t & 255;
        float pos = (float)((s >> 4) + (s & 15));
        int lh = l16 & 7;
        int sA = (lane & 16) + 2 * lh;
        float xA0 = __shfl_sync(0xffffffffu, f0.x, sA);
        float xA1 = __shfl_sync(0xffffffffu, f0.y, sA);
        float xB0 = __shfl_sync(0xffffffffu, f0.x, sA + 1);
        float xB1 = __shfl_sync(0xffffffffu, f0.y, sA + 1);
        float angA = pos * exp2f(-(float)(2 * lh) * 0.8304820237218406f);
        float angB = pos * exp2f(-(float)(2 * lh + 1) * 0.8304820237218406f);
        float sa, ca, sb, cb;
        __sincosf(angA, &sa, &ca);
        __sincosf(angB, &sb, &cb);
        if (l16 < 8) {
            f0.x = fmaf(xA0, ca, -xA1 * sa);
            f0.y = fmaf(xB0, cb, -xB1 * sb);
        } else {
            f0.x = fmaf(xA0, sa, xA1 * ca);
            f0.y = fmaf(xB0, sb, xB1 * cb);
        }
    }

    dp[l16]      = __float22half2_rn(f0);
    dp[l16 + 16] = __float22half2_rn(f1);
    dp[l16 + 32] = __float22half2_rn(f2);
}

// ============================================================================
// Flash attention, fp16 mma.sync m16n8k16, fp32 accum/softmax.
// 128-thread CTAs (4 warps, 64 q-rows), 2 CTAs/SM, double-buffered K/V.
// NEW: P held in registers — the S-accumulator fragment layout IS the PV
// A-fragment layout (no smem round-trip, no P ldmatrix, no syncwarps).
// ============================================================================
#define KS 104
#define VS 104
#define KV_STG   (64 * (KS + VS))                       // halves per stage
#define ATTN_SMEM (2 * KV_STG * 2)                      // 53248 bytes

__global__ __launch_bounds__(128, 2) void attn_kernel()
{
    extern __shared__ __half smh[];
    const uint32_t sbase = smem_u32(smh);

    const int tid  = threadIdx.x;
    const int lane = tid & 31;
    const int wid  = tid >> 5;          // 0..3
    const int quarter = blockIdx.x;     // 0..3 (64 q-rows each)
    const int h    = blockIdx.y;
    const int bf   = blockIdx.z;
    const int g    = h / 3;

    const __half* Qg = g_qh + ((size_t)(bf * NHEADS + h) * SEQ
                               + quarter * 64 + wid * 16) * HEADDIM;
    const __half* Kg = g_kh + (size_t)(bf * NGROUPS + g) * SEQ * HEADDIM;
    const __half* Vg = g_vh + (size_t)(bf * NGROUPS + g) * SEQ * HEADDIM;

    uint32_t qf[6][4];
    {
        const __half* q0 = Qg + (lane >> 2) * HEADDIM;
        const __half* q1 = Qg + ((lane >> 2) + 8) * HEADDIM;
        int cc = 2 * (lane & 3);
#pragma unroll
        for (int j = 0; j < 6; j++) {
            qf[j][0] = *(const uint32_t*)(q0 + j * 16 + cc);
            qf[j][1] = *(const uint32_t*)(q1 + j * 16 + cc);
            qf[j][2] = *(const uint32_t*)(q0 + j * 16 + 8 + cc);
            qf[j][3] = *(const uint32_t*)(q1 + j * 16 + 8 + cc);
        }
    }

    const int idx  = lane >> 3;
    const int lrow = lane & 7;

    auto load_kv = [&](int kt, int st) {
        uint32_t kb = sbase + st * (KV_STG * 2);
        uint32_t vb = kb + 64 * KS * 2;
        const __half* Kc = Kg + (size_t)kt * 64 * HEADDIM;
        const __half* Vc = Vg + (size_t)kt * 64 * HEADDIM;
#pragma unroll
        for (int it = 0; it < 6; it++) {
            int i = tid + it * 128;
            int r = i / 12, c = (i % 12) * 8;
            cp_async16(kb + (r * KS + c) * 2, Kc + r * HEADDIM + c);
            cp_async16(vb + (r * VS + c) * 2, Vc + r * HEADDIM + c);
        }
    };

    float m_a = -INFINITY, m_b = -INFINITY;
    float l_a = 0.f, l_b = 0.f;
    float oacc[12][4];
#pragma unroll
    for (int nt = 0; nt < 12; nt++)
#pragma unroll
        for (int r = 0; r < 4; r++) oacc[nt][r] = 0.f;

    load_kv(0, 0);
    asm volatile("cp.async.commit_group;");

    for (int kt = 0; kt < 4; kt++) {
        __syncthreads();
        if (kt < 3) {
            load_kv(kt + 1, (kt + 1) & 1);
            asm volatile("cp.async.commit_group;");
            asm volatile("cp.async.wait_group 1;");
        } else {
            asm volatile("cp.async.wait_group 0;");
        }
        __syncthreads();

        const int st = kt & 1;
        const uint32_t sKb = sbase + st * (KV_STG * 2);
        const uint32_t sVb = sKb + 64 * KS * 2;

        // ---- S = Q K^T ----
        float sacc[8][4];
#pragma unroll
        for (int nt = 0; nt < 8; nt++)
#pragma unroll
            for (int r = 0; r < 4; r++) sacc[nt][r] = 0.f;

#pragma unroll
        for (int j = 0; j < 6; j++) {
#pragma unroll
            for (int nt2 = 0; nt2 < 4; nt2++) {
                uint32_t r[4];
                ldsm4(r, sKb + ((nt2 * 16 + (idx >> 1) * 8 + lrow) * KS
                                + j * 16 + (idx & 1) * 8) * 2);
                uint32_t b0[2] = {r[0], r[1]};
                uint32_t b1[2] = {r[2], r[3]};
                mma_f16(sacc[2 * nt2], qf[j], b0);
                mma_f16(sacc[2 * nt2 + 1], qf[j], b1);
            }
        }

        // ---- online softmax ----
        float tmax_a = -INFINITY, tmax_b = -INFINITY;
#pragma unroll
        for (int nt = 0; nt < 8; nt++) {
#pragma unroll
            for (int r = 0; r < 4; r++) sacc[nt][r] *= SM_SCALE;
            tmax_a = fmaxf(tmax_a, fmaxf(sacc[nt][0], sacc[nt][1]));
            tmax_b = fmaxf(tmax_b, fmaxf(sacc[nt][2], sacc[nt][3]));
        }
        tmax_a = fmaxf(tmax_a, __shfl_xor_sync(0xffffffffu, tmax_a, 1));
        tmax_a = fmaxf(tmax_a, __shfl_xor_sync(0xffffffffu, tmax_a, 2));
        tmax_b = fmaxf(tmax_b, __shfl_xor_sync(0xffffffffu, tmax_b, 1));
        tmax_b = fmaxf(tmax_b, __shfl_xor_sync(0xffffffffu, tmax_b, 2));

        float mn_a = fmaxf(m_a, tmax_a);
        float mn_b = fmaxf(m_b, tmax_b);
        float al_a = __expf(m_a - mn_a);
        float al_b = __expf(m_b - mn_b);
        m_a = mn_a; m_b = mn_b;

        // ---- exponentiate, pack P fragments in registers ----
        uint32_t pfl[8], pfh[8];    // pfl: rows r (acc 0,1); pfh: rows r+8 (acc 2,3)
        float sum_a = 0.f, sum_b = 0.f;
#pragma unroll
        for (int nt = 0; nt < 8; nt++) {
            float p0 = __expf(sacc[nt][0] - mn_a);
            float p1 = __expf(sacc[nt][1] - mn_a);
            float p2 = __expf(sacc[nt][2] - mn_b);
            float p3 = __expf(sacc[nt][3] - mn_b);
            sum_a += p0 + p1;
            sum_b += p2 + p3;
            pfl[nt] = pack_h2(p0, p1);
            pfh[nt] = pack_h2(p2, p3);
        }
        sum_a += __shfl_xor_sync(0xffffffffu, sum_a, 1);
        sum_a += __shfl_xor_sync(0xffffffffu, sum_a, 2);
        sum_b += __shfl_xor_sync(0xffffffffu, sum_b, 1);
        sum_b += __shfl_xor_sync(0xffffffffu, sum_b, 2);
        l_a = l_a * al_a + sum_a;
        l_b = l_b * al_b + sum_b;

#pragma unroll
        for (int nt = 0; nt < 12; nt++) {
            oacc[nt][0] *= al_a; oacc[nt][1] *= al_a;
            oacc[nt][2] *= al_b; oacc[nt][3] *= al_b;
        }

        // ---- O += P V (P fragments straight from registers) ----
#pragma unroll
        for (int jj = 0; jj < 4; jj++) {
            uint32_t af[4] = {pfl[2 * jj], pfh[2 * jj],
                              pfl[2 * jj + 1], pfh[2 * jj + 1]};
#pragma unroll
            for (int dt2 = 0; dt2 < 6; dt2++) {
                uint32_t r[4];
                ldsm4t(r, sVb + ((jj * 16 + (idx & 1) * 8 + lrow) * VS
                                 + dt2 * 16 + (idx >> 1) * 8) * 2);
                uint32_t b0[2] = {r[0], r[1]};
                uint32_t b1[2] = {r[2], r[3]};
                mma_f16(oacc[2 * dt2], af, b0);
                mma_f16(oacc[2 * dt2 + 1], af, b1);
            }
        }
    }

    float invla = 1.0f / l_a;
    float invlb = 1.0f / l_b;
    int row0 = quarter * 64 + wid * 16 + (lane >> 2);
    __half* o0 = g_oh + (size_t)(bf * SEQ + row0) * DMODEL + h * HEADDIM;
    __half* o1 = g_oh + (size_t)(bf * SEQ + row0 + 8) * DMODEL + h * HEADDIM;
#pragma unroll
    for (int nt = 0; nt < 12; nt++) {
        int col = nt * 8 + 2 * (lane & 3);
        *(__half2*)(o0 + col) = __float22half2_rn(
            make_float2(oacc[nt][0] * invla, oacc[nt][1] * invla));
        *(__half2*)(o1 + col) = __float22half2_rn(
            make_float2(oacc[nt][2] * invlb, oacc[nt][3] * invlb));
    }
}

// ============================================================================
// launch
// ============================================================================
extern "C" void kernel_launch(void* const* d_in, const int* in_sizes, int n_in,
                              void* d_out, int out_size)
{
    const float* x     = (const float*)d_in[0];
    const float* w_qkv = (const float*)d_in[1];
    const float* w_o   = (const float*)d_in[2];
    float* out = (float*)d_out;

    __half *xh_p, *wh_p, *qkvh_p, *oh_p;
    cudaGetSymbolAddress((void**)&xh_p, g_xh);
    cudaGetSymbolAddress((void**)&wh_p, g_wh);
    cudaGetSymbolAddress((void**)&qkvh_p, g_qkvh);
    cudaGetSymbolAddress((void**)&oh_p, g_oh);

    cudaFuncSetAttribute(gemm_f16<__half>,
                         cudaFuncAttributeMaxDynamicSharedMemorySize, GEMM_SMEM);
    cudaFuncSetAttribute(gemm_f16<float>,
                         cudaFuncAttributeMaxDynamicSharedMemorySize, GEMM_SMEM);
    cudaFuncSetAttribute(attn_kernel,
                         cudaFuncAttributeMaxDynamicSharedMemorySize, ATTN_SMEM);

    int n8;

    // convert x -> fp16, w_qkv -> fp16
    n8 = MTOK * DMODEL / 8;
    f32_to_f16_kernel<<<(n8 + 255) / 256, 256>>>((const float4*)x, (uint4*)xh_p, n8);
    n8 = QKV_N * DMODEL / 8;
    f32_to_f16_kernel<<<(n8 + 255) / 256, 256>>>((const float4*)w_qkv, (uint4*)wh_p, n8);

    // 1) QKV projection: qkvh[32768,1920] = xh @ w_qkv^T  (fp16 out, 2 CTAs/SM)
    gemm_f16<__half><<<dim3(QKV_N / 128, MTOK / 128), 128, GEMM_SMEM>>>(
        xh_p, wh_p, qkvh_p, QKV_N, DMODEL);

    // 2) qk-norm + spatial RoPE + transpose (half-warp per vector)
    {
        int total_vec = MTOK * NHEADS + 2 * MTOK * NGROUPS;  // 655360
        int warps = total_vec / 2;                            // 327680
        normrope_kernel<<<warps / 8, 256>>>(qkvh_p);
    }

    // 3) flash attention (fp16 mma, 2 CTAs/SM, P-in-registers)
    attn_kernel<<<dim3(4, NHEADS, BFRAMES), 128, ATTN_SMEM>>>();

    // convert w_o -> fp16
    n8 = DMODEL * DMODEL / 8;
    f32_to_f16_kernel<<<(n8 + 255) / 256, 256>>>((const float4*)w_o, (uint4*)wh_p, n8);

    // 4) output projection: out[32768,1152] = oh @ w_o^T  (fp32 out, 2 CTAs/SM)
    gemm_f16<float><<<dim3(DMODEL / 128, MTOK / 128), 128, GEMM_SMEM>>>(
        oh_p, wh_p, out, DMODEL, DMODEL);
}